// round 2
// baseline (speedup 1.0000x reference)
#include <cuda_runtime.h>
#include <cuda_bf16.h>
#include <math.h>

// ---------------- problem constants ----------------
#define BB 2
#define HH 256
#define WWID 256
#define LL 65536          // H*W
#define CC 180
#define NHD 6
#define HDIM 30
#define WSZ 8
#define NWIN 2048         // B * (H/8) * (W/8)
#define CFFN 360
#define C8 22             // 180 // 8
#define MROWS (BB*LL)     // 131072

// ---------------- scratch (device globals, no allocation) ----------------
__device__ float g_n1   [(size_t)MROWS*CC];
__device__ float g_qkv  [(size_t)MROWS*540];   // reused for h (M x 360)
__device__ float g_attn [(size_t)MROWS*CC];    // pre-proj attention out, reused as n2
__device__ float g_attnf[(size_t)MROWS*CC];    // post-proj attention feature
__device__ float g_conv [(size_t)MROWS*CC];
__device__ float g_xmid [(size_t)MROWS*CC];
__device__ float g_hs   [(size_t)MROWS*CFFN];
__device__ float g_pooled[BB*CC];
__device__ float g_cm    [BB*CC];

__device__ __forceinline__ float gelu_exact(float x) {
    return 0.5f * x * (1.0f + erff(x * 0.70710678118654752f));
}

// ---------------- LayerNorm: 4 warps / block, 1 warp per row ----------------
__global__ void ln_kernel(const float* __restrict__ x,
                          const float* __restrict__ g,
                          const float* __restrict__ b,
                          float* __restrict__ out) {
    int row = blockIdx.x * 4 + (threadIdx.x >> 5);
    int lane = threadIdx.x & 31;
    const float* xr = x + (size_t)row * CC;
    float v[6];
    float s = 0.f;
#pragma unroll
    for (int i = 0; i < 6; i++) {
        int c = lane + 32 * i;
        v[i] = (c < CC) ? xr[c] : 0.f;
        s += v[i];
    }
#pragma unroll
    for (int o = 16; o; o >>= 1) s += __shfl_xor_sync(0xffffffffu, s, o);
    float mean = s * (1.f / CC);
    float vs = 0.f;
#pragma unroll
    for (int i = 0; i < 6; i++) {
        int c = lane + 32 * i;
        if (c < CC) { float d = v[i] - mean; vs += d * d; }
    }
#pragma unroll
    for (int o = 16; o; o >>= 1) vs += __shfl_xor_sync(0xffffffffu, vs, o);
    float rstd = rsqrtf(vs * (1.f / CC) + 1e-5f);
    float* orow = out + (size_t)row * CC;
#pragma unroll
    for (int i = 0; i < 6; i++) {
        int c = lane + 32 * i;
        if (c < CC) orow[c] = (v[i] - mean) * rstd * g[c] + b[c];
    }
}

// ---------------- generic SGEMM: C = A[MxK] @ W[NxK]^T (+epi) ----------------
// EPI: 0 = none, 1 = +bias, 2 = gelu, 3 = +residual
template <int EPI>
__global__ void gemm_kernel(const float* __restrict__ A,
                            const float* __restrict__ Wt,
                            const float* __restrict__ bias,
                            const float* __restrict__ res,
                            float* __restrict__ Cout,
                            int N, int K) {
    extern __shared__ float sm[];
    float* As = sm;                // [180][65]
    float* Bs = sm + 180 * 65;     // [180][65]
    const int row0 = blockIdx.x * 64;
    const int col0 = blockIdx.y * 64;
    const int tid = threadIdx.x;           // 256
    const int tx = tid & 15;               // col group
    const int ty = tid >> 4;               // row group
    float acc[4][4] = {};

    for (int k0 = 0; k0 < K; k0 += 180) {
        for (int idx = tid; idx < 64 * 180; idx += 256) {
            int m = idx / 180, k = idx - m * 180;
            As[k * 65 + m] = A[(size_t)(row0 + m) * K + k0 + k];
        }
        for (int idx = tid; idx < 64 * 180; idx += 256) {
            int n = idx / 180, k = idx - n * 180;
            float val = (col0 + n < N) ? Wt[(size_t)(col0 + n) * K + k0 + k] : 0.f;
            Bs[k * 65 + n] = val;
        }
        __syncthreads();
#pragma unroll 6
        for (int k = 0; k < 180; k++) {
            const float* ap = &As[k * 65 + ty * 4];
            const float* bp = &Bs[k * 65 + tx * 4];
            float a0 = ap[0], a1 = ap[1], a2 = ap[2], a3 = ap[3];
            float b0 = bp[0], b1 = bp[1], b2 = bp[2], b3 = bp[3];
            acc[0][0] += a0 * b0; acc[0][1] += a0 * b1; acc[0][2] += a0 * b2; acc[0][3] += a0 * b3;
            acc[1][0] += a1 * b0; acc[1][1] += a1 * b1; acc[1][2] += a1 * b2; acc[1][3] += a1 * b3;
            acc[2][0] += a2 * b0; acc[2][1] += a2 * b1; acc[2][2] += a2 * b2; acc[2][3] += a2 * b3;
            acc[3][0] += a3 * b0; acc[3][1] += a3 * b1; acc[3][2] += a3 * b2; acc[3][3] += a3 * b3;
        }
        __syncthreads();
    }

#pragma unroll
    for (int i = 0; i < 4; i++) {
        int r = row0 + ty * 4 + i;
#pragma unroll
        for (int j = 0; j < 4; j++) {
            int c = col0 + tx * 4 + j;
            if (c < N) {
                float v = acc[i][j];
                if (EPI == 1) v += bias[c];
                if (EPI == 2) v = gelu_exact(v);
                if (EPI == 3) v += res[(size_t)r * N + c];
                Cout[(size_t)r * N + c] = v;
            }
        }
    }
}

// ---------------- window attention: 1 block / window, 6 heads x 64 tokens ----------------
__global__ void attn_kernel(const float* __restrict__ qkv,
                            const float* __restrict__ b_rel,
                            float* __restrict__ out) {
    extern __shared__ float kv[];   // [64][360]: cols 0..179 = K, 180..359 = V
    const int w = blockIdx.x;
    const int b  = w >> 10;
    const int wy = (w & 1023) >> 5;
    const int wx = w & 31;
    const int tid = threadIdx.x;    // 384

    for (int idx = tid; idx < 64 * 360; idx += 384) {
        int t = idx / 360, c = idx - t * 360;
        int ty = t >> 3, tx = t & 7;
        size_t row = ((size_t)b << 16) + (size_t)(wy * 8 + ty) * 256 + (wx * 8 + tx);
        kv[idx] = qkv[row * 540 + 180 + c];
    }
    __syncthreads();

    const int h = tid / 64;
    const int t = tid & 63;
    const int ty = t >> 3, tx = t & 7;
    size_t row = ((size_t)b << 16) + (size_t)(wy * 8 + ty) * 256 + (wx * 8 + tx);

    float q[HDIM];
    const float* qp = qkv + row * 540 + h * HDIM;
    const float scale = 0.18257418583505536f;  // 30^-0.5
#pragma unroll
    for (int d = 0; d < HDIM; d++) q[d] = qp[d] * scale;

    const float* br = b_rel + h * 4096 + t * 64;
    float m = -1e30f, l = 0.f;
    float o[HDIM] = {};
    for (int j = 0; j < 64; j++) {
        const float* kj = &kv[j * 360 + h * HDIM];
        float s = br[j];
#pragma unroll
        for (int d = 0; d < HDIM; d++) s += q[d] * kj[d];
        float mn = fmaxf(m, s);
        float corr = expf(m - mn);
        float p = expf(s - mn);
        l = l * corr + p;
        const float* vj = &kv[j * 360 + 180 + h * HDIM];
#pragma unroll
        for (int d = 0; d < HDIM; d++) o[d] = o[d] * corr + p * vj[d];
        m = mn;
    }
    float inv = 1.f / l;
    float* op = out + row * CC + h * HDIM;
#pragma unroll
    for (int d = 0; d < HDIM; d++) op[d] = o[d] * inv;
}

// ---------------- depthwise 3x3 SAME conv in NHWC, optional GELU ----------------
__global__ void dwconv_kernel(const float* __restrict__ in,
                              const float* __restrict__ k9,
                              float* __restrict__ out,
                              int Cdim, int do_gelu) {
    const int p = blockIdx.x;          // b*65536 + y*256 + x
    const int c = threadIdx.x;
    const int b = p >> 16;
    const int y = (p >> 8) & 255;
    const int x = p & 255;
    float acc = 0.f;
#pragma unroll
    for (int dy = -1; dy <= 1; dy++) {
        int yy = y + dy;
        if (yy < 0 || yy >= HH) continue;
#pragma unroll
        for (int dx = -1; dx <= 1; dx++) {
            int xx = x + dx;
            if (xx < 0 || xx >= WWID) continue;
            size_t ip = ((size_t)b << 16) + (size_t)yy * 256 + xx;
            acc += in[ip * Cdim + c] * k9[c * 9 + (dy + 1) * 3 + (dx + 1)];
        }
    }
    if (do_gelu) acc = gelu_exact(acc);
    out[(size_t)p * Cdim + c] = acc;
}

// ---------------- mean-pool conv_feat over L into pooled[B][C] ----------------
__global__ void pool_kernel(const float* __restrict__ conv, float* __restrict__ pooled) {
    const int b = blockIdx.x;
    const int chunk = blockIdx.y;   // 256 chunks of 256 rows
    const int c = threadIdx.x;
    float s = 0.f;
    size_t base = ((size_t)b << 16) + (size_t)chunk * 256;
    for (int r = 0; r < 256; r++) s += conv[(base + r) * CC + c];
    atomicAdd(&pooled[b * CC + c], s * (1.f / (float)LL));
}

// ---------------- channel gate ----------------
__global__ void gate_kernel(const float* __restrict__ pooled,
                            const float* __restrict__ w1,
                            const float* __restrict__ w2,
                            float* __restrict__ cm) {
    const int b = blockIdx.x;
    const int tid = threadIdx.x;   // 180
    __shared__ float t1[C8];
    if (tid < C8) {
        float s = 0.f;
        for (int c = 0; c < CC; c++) s += pooled[b * CC + c] * w1[tid * CC + c];
        t1[tid] = gelu_exact(s);
    }
    __syncthreads();
    float s = 0.f;
#pragma unroll
    for (int j = 0; j < C8; j++) s += t1[j] * w2[tid * C8 + j];
    cm[b * CC + tid] = 1.f / (1.f + expf(-s));
}

// ---------------- first residual: xmid = x + attn_feat*cm + conv_feat ----------------
__global__ void resid_kernel(const float* __restrict__ x,
                             const float* __restrict__ attnf,
                             const float* __restrict__ conv,
                             const float* __restrict__ cm,
                             float* __restrict__ xmid) {
    const int row = blockIdx.x;
    const int c = threadIdx.x;
    const int b = row >> 16;
    size_t i = (size_t)row * CC + c;
    xmid[i] = x[i] + attnf[i] * cm[b * CC + c] + conv[i];
}

// ---------------- launch ----------------
extern "C" void kernel_launch(void* const* d_in, const int* in_sizes, int n_in,
                              void* d_out, int out_size) {
    const float* x       = (const float*)d_in[0];
    const float* w_qkv   = (const float*)d_in[1];
    const float* b_rel   = (const float*)d_in[2];
    const float* w_proj  = (const float*)d_in[3];
    const float* b_proj  = (const float*)d_in[4];
    const float* conv_dw = (const float*)d_in[5];
    const float* cg_w1   = (const float*)d_in[6];
    const float* cg_w2   = (const float*)d_in[7];
    const float* ffn_w1  = (const float*)d_in[8];
    const float* ffn_dw  = (const float*)d_in[9];
    const float* ffn_w2  = (const float*)d_in[10];
    const float* n1_g    = (const float*)d_in[11];
    const float* n1_b    = (const float*)d_in[12];
    const float* n2_g    = (const float*)d_in[13];
    const float* n2_b    = (const float*)d_in[14];
    float* out = (float*)d_out;

    float *n1, *qkv, *attn, *attnf, *conv, *xmid, *hs, *pooled, *cm;
    cudaGetSymbolAddress((void**)&n1,    g_n1);
    cudaGetSymbolAddress((void**)&qkv,   g_qkv);
    cudaGetSymbolAddress((void**)&attn,  g_attn);
    cudaGetSymbolAddress((void**)&attnf, g_attnf);
    cudaGetSymbolAddress((void**)&conv,  g_conv);
    cudaGetSymbolAddress((void**)&xmid,  g_xmid);
    cudaGetSymbolAddress((void**)&hs,    g_hs);
    cudaGetSymbolAddress((void**)&pooled, g_pooled);
    cudaGetSymbolAddress((void**)&cm,     g_cm);

    const int GEMM_SMEM = 2 * 180 * 65 * sizeof(float);   // 93600
    const int ATTN_SMEM = 64 * 360 * sizeof(float);       // 92160
    cudaFuncSetAttribute(gemm_kernel<0>, cudaFuncAttributeMaxDynamicSharedMemorySize, GEMM_SMEM);
    cudaFuncSetAttribute(gemm_kernel<1>, cudaFuncAttributeMaxDynamicSharedMemorySize, GEMM_SMEM);
    cudaFuncSetAttribute(gemm_kernel<2>, cudaFuncAttributeMaxDynamicSharedMemorySize, GEMM_SMEM);
    cudaFuncSetAttribute(gemm_kernel<3>, cudaFuncAttributeMaxDynamicSharedMemorySize, GEMM_SMEM);
    cudaFuncSetAttribute(attn_kernel,    cudaFuncAttributeMaxDynamicSharedMemorySize, ATTN_SMEM);

    // 1) ln1: x -> n1
    ln_kernel<<<MROWS / 4, 128>>>(x, n1_g, n1_b, n1);

    // 2) qkv = n1 @ w_qkv^T   (N=540, K=180)
    gemm_kernel<0><<<dim3(MROWS / 64, 9), 256, GEMM_SMEM>>>(n1, w_qkv, nullptr, nullptr, qkv, 540, 180);

    // 3) window attention -> attn (pre-proj, [M x 180])
    attn_kernel<<<NWIN, 384, ATTN_SMEM>>>(qkv, b_rel, attn);

    // 4) proj: attnf = attn @ w_proj^T + b_proj   (N=180, K=180)
    gemm_kernel<1><<<dim3(MROWS / 64, 3), 256, GEMM_SMEM>>>(attn, w_proj, b_proj, nullptr, attnf, 180, 180);

    // 5) conv branch: dwconv(n1) + GELU -> conv
    dwconv_kernel<<<MROWS, CC>>>(n1, conv_dw, conv, CC, 1);

    // 6) pool conv -> pooled
    cudaMemsetAsync(pooled, 0, BB * CC * sizeof(float));
    pool_kernel<<<dim3(BB, 256), CC>>>(conv, pooled);

    // 7) channel gate -> cm
    gate_kernel<<<BB, CC>>>(pooled, cg_w1, cg_w2, cm);

    // 8) residual: xmid = x + attnf*cm + conv
    resid_kernel<<<MROWS, CC>>>(x, attnf, conv, cm, xmid);

    // 9) ln2: xmid -> n2 (reuse attn buffer)
    ln_kernel<<<MROWS / 4, 128>>>(xmid, n2_g, n2_b, attn);

    // 10) ffn1: h = gelu(n2 @ ffn_w1^T)  (N=360, K=180), h stored in qkv buffer
    gemm_kernel<2><<<dim3(MROWS / 64, 6), 256, GEMM_SMEM>>>(attn, ffn_w1, nullptr, nullptr, qkv, 360, 180);

    // 11) ffn dwconv: hs = dwconv(h) (no gelu), Cdim=360
    dwconv_kernel<<<MROWS, CFFN>>>(qkv, ffn_dw, hs, CFFN, 0);

    // 12) ffn2 + residual: out = xmid + hs @ ffn_w2^T   (N=180, K=360)
    gemm_kernel<3><<<dim3(MROWS / 64, 3), 256, GEMM_SMEM>>>(hs, ffn_w2, nullptr, xmid, out, 180, 360);
}

// round 3
// speedup vs baseline: 2.5567x; 2.5567x over previous
#include <cuda_runtime.h>
#include <cuda_bf16.h>
#include <math.h>
#include <cstdint>

// ---------------- problem constants ----------------
#define BB 2
#define HH 256
#define WWID 256
#define LL 65536          // H*W
#define CC 180
#define NHD 6
#define HDIM 30
#define WSZ 8
#define NWIN 2048         // B * (H/8) * (W/8)
#define CFFN 360
#define C8 22             // 180 // 8
#define MROWS (BB*LL)     // 131072

// ---------------- scratch (device globals, no allocation) ----------------
__device__ float g_n1   [(size_t)MROWS*CC];
__device__ float g_qkv  [(size_t)MROWS*540];   // reused for h (M x 360)
__device__ float g_attn [(size_t)MROWS*CC];    // pre-proj attention out, reused as n2
__device__ float g_attnf[(size_t)MROWS*CC];    // post-proj attention feature
__device__ float g_conv [(size_t)MROWS*CC];
__device__ float g_xmid [(size_t)MROWS*CC];
__device__ float g_hs   [(size_t)MROWS*CFFN];
__device__ float g_pooled[BB*CC];
__device__ float g_cm    [BB*CC];
__device__ float g_wr    [259200];             // tf32-rounded weights

#define WR_QKV  0
#define WR_PROJ 97200
#define WR_FFN1 129600
#define WR_FFN2 194400

__device__ __forceinline__ float gelu_exact(float x) {
    return 0.5f * x * (1.0f + erff(x * 0.70710678118654752f));
}

__device__ __forceinline__ uint32_t f2tf32(float v) {
    uint32_t r;
    asm("cvt.rna.tf32.f32 %0, %1;" : "=r"(r) : "f"(v));
    return r;
}

// ---------------- round weights to tf32 once ----------------
__global__ void roundw_kernel(const float* __restrict__ src, float* __restrict__ dst, int n) {
    int i = blockIdx.x * 256 + threadIdx.x;
    if (i < n) dst[i] = __uint_as_float(f2tf32(src[i]));
}

// ---------------- LayerNorm: 4 warps / block, 1 warp per row ----------------
__global__ void ln_kernel(const float* __restrict__ x,
                          const float* __restrict__ g,
                          const float* __restrict__ b,
                          float* __restrict__ out) {
    int row = blockIdx.x * 4 + (threadIdx.x >> 5);
    int lane = threadIdx.x & 31;
    const float* xr = x + (size_t)row * CC;
    float v[6];
    float s = 0.f;
#pragma unroll
    for (int i = 0; i < 6; i++) {
        int c = lane + 32 * i;
        v[i] = (c < CC) ? xr[c] : 0.f;
        s += v[i];
    }
#pragma unroll
    for (int o = 16; o; o >>= 1) s += __shfl_xor_sync(0xffffffffu, s, o);
    float mean = s * (1.f / CC);
    float vs = 0.f;
#pragma unroll
    for (int i = 0; i < 6; i++) {
        int c = lane + 32 * i;
        if (c < CC) { float d = v[i] - mean; vs += d * d; }
    }
#pragma unroll
    for (int o = 16; o; o >>= 1) vs += __shfl_xor_sync(0xffffffffu, vs, o);
    float rstd = rsqrtf(vs * (1.f / CC) + 1e-5f);
    float* orow = out + (size_t)row * CC;
#pragma unroll
    for (int i = 0; i < 6; i++) {
        int c = lane + 32 * i;
        if (c < CC) orow[c] = (v[i] - mean) * rstd * g[c] + b[c];
    }
}

// ---------------- tensor-core GEMM: C = A[MxK] @ W[NxK]^T (+epi) ----------------
// tf32 HMMA m16n8k8. Block: 256 thr = 8 warps, tile 128x64, BK=32, double-buffered cp.async.
// EPI: 0 = none, 1 = +bias, 2 = gelu, 3 = +residual
template <int EPI>
__global__ void __launch_bounds__(256) mma_gemm(const float* __restrict__ A,
                                                const float* __restrict__ Wt,
                                                const float* __restrict__ bias,
                                                const float* __restrict__ res,
                                                float* __restrict__ Cout,
                                                int N, int K) {
    extern __shared__ float sm[];
    float* As = sm;                       // [2][128][36]
    float* Bs = sm + 2 * 128 * 36;        // [2][64][36]
    const int tid  = threadIdx.x;
    const int row0 = blockIdx.x * 128;
    const int col0 = blockIdx.y * 64;
    const int NS   = (K + 31) >> 5;
    const int wid  = tid >> 5;
    const int lane = tid & 31;
    const int warpm = wid >> 1;           // 0..3
    const int warpn = wid & 1;            // 0..1
    const int gr = lane >> 2;             // 0..7
    const int cq = lane & 3;              // 0..3

    uint32_t sA = (uint32_t)__cvta_generic_to_shared(As);
    uint32_t sB = (uint32_t)__cvta_generic_to_shared(Bs);

    auto issue = [&](int s) {
        const int k0  = s << 5;
        const int buf = s & 1;
        uint32_t abase = sA + buf * (128 * 36 * 4);
        uint32_t bbase = sB + buf * (64 * 36 * 4);
#pragma unroll
        for (int i = 0; i < 4; i++) {                 // A: 1024 16B chunks
            int cid = tid + 256 * i;
            int m = cid >> 3, kc = (cid & 7) << 2;
            const float* g = A + (size_t)(row0 + m) * K + k0 + kc;
            uint32_t sa = abase + (uint32_t)(m * 36 + kc) * 4;
            unsigned p = (k0 + kc < K) ? 16u : 0u;
            asm volatile("cp.async.cg.shared.global [%0], [%1], 16, %2;\n"
                         :: "r"(sa), "l"(g), "r"(p));
        }
#pragma unroll
        for (int i = 0; i < 2; i++) {                 // B: 512 16B chunks
            int cid = tid + 256 * i;
            int n = cid >> 3, kc = (cid & 7) << 2;
            const float* g = Wt + (size_t)(col0 + n) * K + k0 + kc;
            uint32_t sb = bbase + (uint32_t)(n * 36 + kc) * 4;
            unsigned p = (col0 + n < N && k0 + kc < K) ? 16u : 0u;
            asm volatile("cp.async.cg.shared.global [%0], [%1], 16, %2;\n"
                         :: "r"(sb), "l"(g), "r"(p));
        }
        asm volatile("cp.async.commit_group;\n");
    };

    float acc[2][4][4];
#pragma unroll
    for (int a = 0; a < 2; a++)
#pragma unroll
        for (int b = 0; b < 4; b++)
#pragma unroll
            for (int c = 0; c < 4; c++) acc[a][b][c] = 0.f;

    issue(0);
    for (int s = 0; s < NS; s++) {
        if (s + 1 < NS) {
            issue(s + 1);
            asm volatile("cp.async.wait_group 1;\n");
        } else {
            asm volatile("cp.async.wait_group 0;\n");
        }
        __syncthreads();
        const float* Ab = As + (s & 1) * (128 * 36);
        const float* Bb = Bs + (s & 1) * (64 * 36);
#pragma unroll
        for (int kk = 0; kk < 4; kk++) {
            uint32_t afr[2][4], bfr[4][2];
#pragma unroll
            for (int mt = 0; mt < 2; mt++) {
                const float* p = Ab + (warpm * 32 + mt * 16 + gr) * 36 + kk * 8 + cq;
                afr[mt][0] = f2tf32(p[0]);
                afr[mt][1] = f2tf32(p[8 * 36]);
                afr[mt][2] = f2tf32(p[4]);
                afr[mt][3] = f2tf32(p[8 * 36 + 4]);
            }
#pragma unroll
            for (int nt = 0; nt < 4; nt++) {
                const float* p = Bb + (warpn * 32 + nt * 8 + gr) * 36 + kk * 8 + cq;
                bfr[nt][0] = __float_as_uint(p[0]);   // weights pre-rounded
                bfr[nt][1] = __float_as_uint(p[4]);
            }
#pragma unroll
            for (int mt = 0; mt < 2; mt++)
#pragma unroll
                for (int nt = 0; nt < 4; nt++) {
                    asm volatile(
                        "mma.sync.aligned.m16n8k8.row.col.f32.tf32.tf32.f32 "
                        "{%0,%1,%2,%3},{%4,%5,%6,%7},{%8,%9},{%0,%1,%2,%3};\n"
                        : "+f"(acc[mt][nt][0]), "+f"(acc[mt][nt][1]),
                          "+f"(acc[mt][nt][2]), "+f"(acc[mt][nt][3])
                        : "r"(afr[mt][0]), "r"(afr[mt][1]), "r"(afr[mt][2]), "r"(afr[mt][3]),
                          "r"(bfr[nt][0]), "r"(bfr[nt][1]));
                }
        }
        __syncthreads();
    }

    // epilogue: thread owns rows (r0, r0+8), cols (cb, cb+1) per (mt, nt) tile
#pragma unroll
    for (int mt = 0; mt < 2; mt++) {
        int r0 = row0 + warpm * 32 + mt * 16 + gr;
#pragma unroll
        for (int nt = 0; nt < 4; nt++) {
            int cb = col0 + warpn * 32 + nt * 8 + cq * 2;
            if (cb < N) {
                float v00 = acc[mt][nt][0], v01 = acc[mt][nt][1];
                float v10 = acc[mt][nt][2], v11 = acc[mt][nt][3];
                if (EPI == 1) { float b0 = bias[cb], b1 = bias[cb + 1];
                                v00 += b0; v01 += b1; v10 += b0; v11 += b1; }
                if (EPI == 2) { v00 = gelu_exact(v00); v01 = gelu_exact(v01);
                                v10 = gelu_exact(v10); v11 = gelu_exact(v11); }
                if (EPI == 3) {
                    const float2 r0v = *(const float2*)&res[(size_t)r0 * N + cb];
                    const float2 r1v = *(const float2*)&res[(size_t)(r0 + 8) * N + cb];
                    v00 += r0v.x; v01 += r0v.y; v10 += r1v.x; v11 += r1v.y;
                }
                *(float2*)&Cout[(size_t)r0 * N + cb]       = make_float2(v00, v01);
                *(float2*)&Cout[(size_t)(r0 + 8) * N + cb] = make_float2(v10, v11);
            }
        }
    }
}

// ---------------- window attention: 1 block / window, 6 heads x 64 tokens ----------------
__global__ void attn_kernel(const float* __restrict__ qkv,
                            const float* __restrict__ b_rel,
                            float* __restrict__ out) {
    extern __shared__ float kv[];   // [64][360]: cols 0..179 = K, 180..359 = V
    const int w = blockIdx.x;
    const int b  = w >> 10;
    const int wy = (w & 1023) >> 5;
    const int wx = w & 31;
    const int tid = threadIdx.x;    // 384

    for (int idx = tid; idx < 64 * 360; idx += 384) {
        int t = idx / 360, c = idx - t * 360;
        int ty = t >> 3, tx = t & 7;
        size_t row = ((size_t)b << 16) + (size_t)(wy * 8 + ty) * 256 + (wx * 8 + tx);
        kv[idx] = qkv[row * 540 + 180 + c];
    }
    __syncthreads();

    const int h = tid / 64;
    const int t = tid & 63;
    const int ty = t >> 3, tx = t & 7;
    size_t row = ((size_t)b << 16) + (size_t)(wy * 8 + ty) * 256 + (wx * 8 + tx);

    float q[HDIM];
    const float* qp = qkv + row * 540 + h * HDIM;
    const float scale = 0.18257418583505536f;  // 30^-0.5
#pragma unroll
    for (int d = 0; d < HDIM; d++) q[d] = qp[d] * scale;

    const float* br = b_rel + h * 4096 + t * 64;
    float m = -1e30f, l = 0.f;
    float o[HDIM] = {};
    for (int j = 0; j < 64; j++) {
        const float* kj = &kv[j * 360 + h * HDIM];
        float s = br[j];
#pragma unroll
        for (int d = 0; d < HDIM; d++) s += q[d] * kj[d];
        float mn = fmaxf(m, s);
        float corr = expf(m - mn);
        float p = expf(s - mn);
        l = l * corr + p;
        const float* vj = &kv[j * 360 + 180 + h * HDIM];
#pragma unroll
        for (int d = 0; d < HDIM; d++) o[d] = o[d] * corr + p * vj[d];
        m = mn;
    }
    float inv = 1.f / l;
    float* op = out + row * CC + h * HDIM;
#pragma unroll
    for (int d = 0; d < HDIM; d++) op[d] = o[d] * inv;
}

// ---------------- depthwise 3x3 SAME conv in NHWC, optional GELU ----------------
__global__ void dwconv_kernel(const float* __restrict__ in,
                              const float* __restrict__ k9,
                              float* __restrict__ out,
                              int Cdim, int do_gelu) {
    const int p = blockIdx.x;          // b*65536 + y*256 + x
    const int c = threadIdx.x;
    const int b = p >> 16;
    const int y = (p >> 8) & 255;
    const int x = p & 255;
    float acc = 0.f;
#pragma unroll
    for (int dy = -1; dy <= 1; dy++) {
        int yy = y + dy;
        if (yy < 0 || yy >= HH) continue;
#pragma unroll
        for (int dx = -1; dx <= 1; dx++) {
            int xx = x + dx;
            if (xx < 0 || xx >= WWID) continue;
            size_t ip = ((size_t)b << 16) + (size_t)yy * 256 + xx;
            acc += in[ip * Cdim + c] * k9[c * 9 + (dy + 1) * 3 + (dx + 1)];
        }
    }
    if (do_gelu) acc = gelu_exact(acc);
    out[(size_t)p * Cdim + c] = acc;
}

// ---------------- mean-pool conv_feat over L into pooled[B][C] ----------------
__global__ void pool_kernel(const float* __restrict__ conv, float* __restrict__ pooled) {
    const int b = blockIdx.x;
    const int chunk = blockIdx.y;   // 256 chunks of 256 rows
    const int c = threadIdx.x;
    float s = 0.f;
    size_t base = ((size_t)b << 16) + (size_t)chunk * 256;
    for (int r = 0; r < 256; r++) s += conv[(base + r) * CC + c];
    atomicAdd(&pooled[b * CC + c], s * (1.f / (float)LL));
}

// ---------------- channel gate ----------------
__global__ void gate_kernel(const float* __restrict__ pooled,
                            const float* __restrict__ w1,
                            const float* __restrict__ w2,
                            float* __restrict__ cm) {
    const int b = blockIdx.x;
    const int tid = threadIdx.x;   // 180
    __shared__ float t1[C8];
    if (tid < C8) {
        float s = 0.f;
        for (int c = 0; c < CC; c++) s += pooled[b * CC + c] * w1[tid * CC + c];
        t1[tid] = gelu_exact(s);
    }
    __syncthreads();
    float s = 0.f;
#pragma unroll
    for (int j = 0; j < C8; j++) s += t1[j] * w2[tid * C8 + j];
    cm[b * CC + tid] = 1.f / (1.f + expf(-s));
}

// ---------------- first residual: xmid = x + attn_feat*cm + conv_feat ----------------
__global__ void resid_kernel(const float* __restrict__ x,
                             const float* __restrict__ attnf,
                             const float* __restrict__ conv,
                             const float* __restrict__ cm,
                             float* __restrict__ xmid) {
    const int row = blockIdx.x;
    const int c = threadIdx.x;
    const int b = row >> 16;
    size_t i = (size_t)row * CC + c;
    xmid[i] = x[i] + attnf[i] * cm[b * CC + c] + conv[i];
}

// ---------------- launch ----------------
extern "C" void kernel_launch(void* const* d_in, const int* in_sizes, int n_in,
                              void* d_out, int out_size) {
    const float* x       = (const float*)d_in[0];
    const float* w_qkv   = (const float*)d_in[1];
    const float* b_rel   = (const float*)d_in[2];
    const float* w_proj  = (const float*)d_in[3];
    const float* b_proj  = (const float*)d_in[4];
    const float* conv_dw = (const float*)d_in[5];
    const float* cg_w1   = (const float*)d_in[6];
    const float* cg_w2   = (const float*)d_in[7];
    const float* ffn_w1  = (const float*)d_in[8];
    const float* ffn_dw  = (const float*)d_in[9];
    const float* ffn_w2  = (const float*)d_in[10];
    const float* n1_g    = (const float*)d_in[11];
    const float* n1_b    = (const float*)d_in[12];
    const float* n2_g    = (const float*)d_in[13];
    const float* n2_b    = (const float*)d_in[14];
    float* out = (float*)d_out;

    float *n1, *qkv, *attn, *attnf, *conv, *xmid, *hs, *pooled, *cm, *wr;
    cudaGetSymbolAddress((void**)&n1,    g_n1);
    cudaGetSymbolAddress((void**)&qkv,   g_qkv);
    cudaGetSymbolAddress((void**)&attn,  g_attn);
    cudaGetSymbolAddress((void**)&attnf, g_attnf);
    cudaGetSymbolAddress((void**)&conv,  g_conv);
    cudaGetSymbolAddress((void**)&xmid,  g_xmid);
    cudaGetSymbolAddress((void**)&hs,    g_hs);
    cudaGetSymbolAddress((void**)&pooled, g_pooled);
    cudaGetSymbolAddress((void**)&cm,     g_cm);
    cudaGetSymbolAddress((void**)&wr,     g_wr);

    const int GEMM_SMEM = (2 * 128 * 36 + 2 * 64 * 36) * sizeof(float);  // 55296
    const int ATTN_SMEM = 64 * 360 * sizeof(float);                      // 92160
    cudaFuncSetAttribute(mma_gemm<0>, cudaFuncAttributeMaxDynamicSharedMemorySize, GEMM_SMEM);
    cudaFuncSetAttribute(mma_gemm<1>, cudaFuncAttributeMaxDynamicSharedMemorySize, GEMM_SMEM);
    cudaFuncSetAttribute(mma_gemm<2>, cudaFuncAttributeMaxDynamicSharedMemorySize, GEMM_SMEM);
    cudaFuncSetAttribute(mma_gemm<3>, cudaFuncAttributeMaxDynamicSharedMemorySize, GEMM_SMEM);
    cudaFuncSetAttribute(attn_kernel, cudaFuncAttributeMaxDynamicSharedMemorySize, ATTN_SMEM);

    // 0) round weights to tf32 (weights: B operands use pre-rounded copies)
    roundw_kernel<<<(97200 + 255) / 256, 256>>>(w_qkv,  wr + WR_QKV,  97200);
    roundw_kernel<<<(32400 + 255) / 256, 256>>>(w_proj, wr + WR_PROJ, 32400);
    roundw_kernel<<<(64800 + 255) / 256, 256>>>(ffn_w1, wr + WR_FFN1, 64800);
    roundw_kernel<<<(64800 + 255) / 256, 256>>>(ffn_w2, wr + WR_FFN2, 64800);

    // 1) ln1: x -> n1
    ln_kernel<<<MROWS / 4, 128>>>(x, n1_g, n1_b, n1);

    // 2) qkv = n1 @ w_qkv^T   (N=540, K=180)
    mma_gemm<0><<<dim3(MROWS / 128, 9), 256, GEMM_SMEM>>>(n1, wr + WR_QKV, nullptr, nullptr, qkv, 540, 180);

    // 3) window attention -> attn (pre-proj, [M x 180])
    attn_kernel<<<NWIN, 384, ATTN_SMEM>>>(qkv, b_rel, attn);

    // 4) proj: attnf = attn @ w_proj^T + b_proj   (N=180, K=180)
    mma_gemm<1><<<dim3(MROWS / 128, 3), 256, GEMM_SMEM>>>(attn, wr + WR_PROJ, b_proj, nullptr, attnf, 180, 180);

    // 5) conv branch: dwconv(n1) + GELU -> conv
    dwconv_kernel<<<MROWS, CC>>>(n1, conv_dw, conv, CC, 1);

    // 6) pool conv -> pooled
    cudaMemsetAsync(pooled, 0, BB * CC * sizeof(float));
    pool_kernel<<<dim3(BB, 256), CC>>>(conv, pooled);

    // 7) channel gate -> cm
    gate_kernel<<<BB, CC>>>(pooled, cg_w1, cg_w2, cm);

    // 8) residual: xmid = x + attnf*cm + conv
    resid_kernel<<<MROWS, CC>>>(x, attnf, conv, cm, xmid);

    // 9) ln2: xmid -> n2 (reuse attn buffer)
    ln_kernel<<<MROWS / 4, 128>>>(xmid, n2_g, n2_b, attn);

    // 10) ffn1: h = gelu(n2 @ ffn_w1^T)  (N=360, K=180), h stored in qkv buffer
    mma_gemm<2><<<dim3(MROWS / 128, 6), 256, GEMM_SMEM>>>(attn, wr + WR_FFN1, nullptr, nullptr, qkv, 360, 180);

    // 11) ffn dwconv: hs = dwconv(h) (no gelu), Cdim=360
    dwconv_kernel<<<MROWS, CFFN>>>(qkv, ffn_dw, hs, CFFN, 0);

    // 12) ffn2 + residual: out = xmid + hs @ ffn_w2^T   (N=180, K=360)
    mma_gemm<3><<<dim3(MROWS / 128, 3), 256, GEMM_SMEM>>>(hs, wr + WR_FFN2, nullptr, xmid, out, 180, 360);
}

// round 4
// speedup vs baseline: 3.1662x; 1.2384x over previous
#include <cuda_runtime.h>
#include <cuda_bf16.h>
#include <math.h>
#include <cstdint>

// ---------------- problem constants ----------------
#define BB 2
#define HH 256
#define WWID 256
#define LL 65536          // H*W
#define CC 180
#define NHD 6
#define HDIM 30
#define WSZ 8
#define NWIN 2048         // B * (H/8) * (W/8)
#define CFFN 360
#define C8 22             // 180 // 8
#define MROWS (BB*LL)     // 131072

// ---------------- scratch (device globals, no allocation) ----------------
__device__ float g_n1   [(size_t)MROWS*CC];
__device__ float g_qkv  [(size_t)MROWS*540];   // reused for h (M x 360)
__device__ float g_attn [(size_t)MROWS*CC];    // pre-proj attention out, reused as n2
__device__ float g_attnf[(size_t)MROWS*CC];    // post-proj attention feature
__device__ float g_conv [(size_t)MROWS*CC];
__device__ float g_xmid [(size_t)MROWS*CC];
__device__ float g_hs   [(size_t)MROWS*CFFN];
__device__ float g_pooled[BB*CC];
__device__ float g_cm    [BB*CC];
__device__ float g_wr    [259200];             // tf32-rounded weights

#define WR_QKV  0
#define WR_PROJ 97200
#define WR_FFN1 129600
#define WR_FFN2 194400

__device__ __forceinline__ float gelu_exact(float x) {
    return 0.5f * x * (1.0f + erff(x * 0.70710678118654752f));
}

__device__ __forceinline__ uint32_t f2tf32(float v) {
    uint32_t r;
    asm("cvt.rna.tf32.f32 %0, %1;" : "=r"(r) : "f"(v));
    return r;
}
__device__ __forceinline__ float tf32r(float v) { return __uint_as_float(f2tf32(v)); }

// ---------------- round weights to tf32 once ----------------
__global__ void roundw_kernel(const float* __restrict__ src, float* __restrict__ dst, int n) {
    int i = blockIdx.x * 256 + threadIdx.x;
    if (i < n) dst[i] = tf32r(src[i]);
}

// ---------------- LayerNorm (emits tf32-rounded output) ----------------
__global__ void ln_kernel(const float* __restrict__ x,
                          const float* __restrict__ g,
                          const float* __restrict__ b,
                          float* __restrict__ out) {
    int row = blockIdx.x * 4 + (threadIdx.x >> 5);
    int lane = threadIdx.x & 31;
    const float* xr = x + (size_t)row * CC;
    float v[6];
    float s = 0.f;
#pragma unroll
    for (int i = 0; i < 6; i++) {
        int c = lane + 32 * i;
        v[i] = (c < CC) ? xr[c] : 0.f;
        s += v[i];
    }
#pragma unroll
    for (int o = 16; o; o >>= 1) s += __shfl_xor_sync(0xffffffffu, s, o);
    float mean = s * (1.f / CC);
    float vs = 0.f;
#pragma unroll
    for (int i = 0; i < 6; i++) {
        int c = lane + 32 * i;
        if (c < CC) { float d = v[i] - mean; vs += d * d; }
    }
#pragma unroll
    for (int o = 16; o; o >>= 1) vs += __shfl_xor_sync(0xffffffffu, vs, o);
    float rstd = rsqrtf(vs * (1.f / CC) + 1e-5f);
    float* orow = out + (size_t)row * CC;
#pragma unroll
    for (int i = 0; i < 6; i++) {
        int c = lane + 32 * i;
        if (c < CC) orow[c] = tf32r((v[i] - mean) * rstd * g[c] + b[c]);
    }
}

// ---------------- fused: xmid = x + attnf*cm + conv; n2 = tf32(LN(xmid)) ----------------
__global__ void resid_ln_kernel(const float* __restrict__ x,
                                const float* __restrict__ attnf,
                                const float* __restrict__ conv,
                                const float* __restrict__ cm,
                                const float* __restrict__ g,
                                const float* __restrict__ b,
                                float* __restrict__ xmid,
                                float* __restrict__ n2) {
    int row = blockIdx.x * 4 + (threadIdx.x >> 5);
    int lane = threadIdx.x & 31;
    int bb = row >> 16;
    size_t base = (size_t)row * CC;
    float v[6];
    float s = 0.f;
#pragma unroll
    for (int i = 0; i < 6; i++) {
        int c = lane + 32 * i;
        if (c < CC) {
            float xv = x[base + c] + attnf[base + c] * cm[bb * CC + c] + conv[base + c];
            xmid[base + c] = xv;
            v[i] = xv;
        } else v[i] = 0.f;
        s += v[i];
    }
#pragma unroll
    for (int o = 16; o; o >>= 1) s += __shfl_xor_sync(0xffffffffu, s, o);
    float mean = s * (1.f / CC);
    float vs = 0.f;
#pragma unroll
    for (int i = 0; i < 6; i++) {
        int c = lane + 32 * i;
        if (c < CC) { float d = v[i] - mean; vs += d * d; }
    }
#pragma unroll
    for (int o = 16; o; o >>= 1) vs += __shfl_xor_sync(0xffffffffu, vs, o);
    float rstd = rsqrtf(vs * (1.f / CC) + 1e-5f);
#pragma unroll
    for (int i = 0; i < 6; i++) {
        int c = lane + 32 * i;
        if (c < CC) n2[base + c] = tf32r((v[i] - mean) * rstd * g[c] + b[c]);
    }
}

// ---------------- tensor-core GEMM: C = A[MxK] @ W[NxK]^T (+epi) ----------------
// A and W are tf32-pre-rounded by their producers. EPI: 0=none 1=+bias 2=gelu 3=+residual
template <int EPI>
__global__ void __launch_bounds__(256) mma_gemm(const float* __restrict__ A,
                                                const float* __restrict__ Wt,
                                                const float* __restrict__ bias,
                                                const float* __restrict__ res,
                                                float* __restrict__ Cout,
                                                int N, int K) {
    extern __shared__ float sm[];
    float* As = sm;                       // [2][128][36]
    float* Bs = sm + 2 * 128 * 36;        // [2][64][36]
    const int tid  = threadIdx.x;
    const int row0 = blockIdx.x * 128;
    const int col0 = blockIdx.y * 64;
    const int NS   = (K + 31) >> 5;
    const int wid  = tid >> 5;
    const int lane = tid & 31;
    const int warpm = wid >> 1;           // 0..3
    const int warpn = wid & 1;            // 0..1
    const int gr = lane >> 2;             // 0..7
    const int cq = lane & 3;              // 0..3

    uint32_t sA = (uint32_t)__cvta_generic_to_shared(As);
    uint32_t sB = (uint32_t)__cvta_generic_to_shared(Bs);

    auto issue = [&](int s) {
        const int k0  = s << 5;
        const int buf = s & 1;
        uint32_t abase = sA + buf * (128 * 36 * 4);
        uint32_t bbase = sB + buf * (64 * 36 * 4);
#pragma unroll
        for (int i = 0; i < 4; i++) {                 // A: 1024 16B chunks
            int cid = tid + 256 * i;
            int m = cid >> 3, kc = (cid & 7) << 2;
            const float* g = A + (size_t)(row0 + m) * K + k0 + kc;
            uint32_t sa = abase + (uint32_t)(m * 36 + kc) * 4;
            unsigned p = (k0 + kc < K) ? 16u : 0u;
            asm volatile("cp.async.cg.shared.global [%0], [%1], 16, %2;\n"
                         :: "r"(sa), "l"(g), "r"(p));
        }
#pragma unroll
        for (int i = 0; i < 2; i++) {                 // B: 512 16B chunks
            int cid = tid + 256 * i;
            int n = cid >> 3, kc = (cid & 7) << 2;
            const float* g = Wt + (size_t)(col0 + n) * K + k0 + kc;
            uint32_t sb = bbase + (uint32_t)(n * 36 + kc) * 4;
            unsigned p = (col0 + n < N && k0 + kc < K) ? 16u : 0u;
            asm volatile("cp.async.cg.shared.global [%0], [%1], 16, %2;\n"
                         :: "r"(sb), "l"(g), "r"(p));
        }
        asm volatile("cp.async.commit_group;\n");
    };

    float acc[2][4][4];
#pragma unroll
    for (int a = 0; a < 2; a++)
#pragma unroll
        for (int b = 0; b < 4; b++)
#pragma unroll
            for (int c = 0; c < 4; c++) acc[a][b][c] = 0.f;

    issue(0);
    for (int s = 0; s < NS; s++) {
        if (s + 1 < NS) {
            issue(s + 1);
            asm volatile("cp.async.wait_group 1;\n");
        } else {
            asm volatile("cp.async.wait_group 0;\n");
        }
        __syncthreads();
        const float* Ab = As + (s & 1) * (128 * 36);
        const float* Bb = Bs + (s & 1) * (64 * 36);
#pragma unroll
        for (int kk = 0; kk < 4; kk++) {
            uint32_t afr[2][4], bfr[4][2];
#pragma unroll
            for (int mt = 0; mt < 2; mt++) {
                const float* p = Ab + (warpm * 32 + mt * 16 + gr) * 36 + kk * 8 + cq;
                afr[mt][0] = __float_as_uint(p[0]);
                afr[mt][1] = __float_as_uint(p[8 * 36]);
                afr[mt][2] = __float_as_uint(p[4]);
                afr[mt][3] = __float_as_uint(p[8 * 36 + 4]);
            }
#pragma unroll
            for (int nt = 0; nt < 4; nt++) {
                const float* p = Bb + (warpn * 32 + nt * 8 + gr) * 36 + kk * 8 + cq;
                bfr[nt][0] = __float_as_uint(p[0]);
                bfr[nt][1] = __float_as_uint(p[4]);
            }
#pragma unroll
            for (int mt = 0; mt < 2; mt++)
#pragma unroll
                for (int nt = 0; nt < 4; nt++) {
                    asm volatile(
                        "mma.sync.aligned.m16n8k8.row.col.f32.tf32.tf32.f32 "
                        "{%0,%1,%2,%3},{%4,%5,%6,%7},{%8,%9},{%0,%1,%2,%3};\n"
                        : "+f"(acc[mt][nt][0]), "+f"(acc[mt][nt][1]),
                          "+f"(acc[mt][nt][2]), "+f"(acc[mt][nt][3])
                        : "r"(afr[mt][0]), "r"(afr[mt][1]), "r"(afr[mt][2]), "r"(afr[mt][3]),
                          "r"(bfr[nt][0]), "r"(bfr[nt][1]));
                }
        }
        __syncthreads();
    }

#pragma unroll
    for (int mt = 0; mt < 2; mt++) {
        int r0 = row0 + warpm * 32 + mt * 16 + gr;
#pragma unroll
        for (int nt = 0; nt < 4; nt++) {
            int cb = col0 + warpn * 32 + nt * 8 + cq * 2;
            if (cb < N) {
                float v00 = acc[mt][nt][0], v01 = acc[mt][nt][1];
                float v10 = acc[mt][nt][2], v11 = acc[mt][nt][3];
                if (EPI == 1) { float b0 = bias[cb], b1 = bias[cb + 1];
                                v00 += b0; v01 += b1; v10 += b0; v11 += b1; }
                if (EPI == 2) { v00 = gelu_exact(v00); v01 = gelu_exact(v01);
                                v10 = gelu_exact(v10); v11 = gelu_exact(v11); }
                if (EPI == 3) {
                    const float2 r0v = *(const float2*)&res[(size_t)r0 * N + cb];
                    const float2 r1v = *(const float2*)&res[(size_t)(r0 + 8) * N + cb];
                    v00 += r0v.x; v01 += r0v.y; v10 += r1v.x; v11 += r1v.y;
                }
                *(float2*)&Cout[(size_t)r0 * N + cb]       = make_float2(v00, v01);
                *(float2*)&Cout[(size_t)(r0 + 8) * N + cb] = make_float2(v10, v11);
            }
        }
    }
}

// ---------------- window attention (no-max softmax: scores provably small) ----------------
__global__ void attn_kernel(const float* __restrict__ qkv,
                            const float* __restrict__ b_rel,
                            float* __restrict__ out) {
    extern __shared__ float kv[];   // [64][360]: cols 0..179 = K, 180..359 = V
    const int w = blockIdx.x;
    const int b  = w >> 10;
    const int wy = (w & 1023) >> 5;
    const int wx = w & 31;
    const int tid = threadIdx.x;    // 384

    for (int idx = tid; idx < 64 * 360; idx += 384) {
        int t = idx / 360, c = idx - t * 360;
        int ty = t >> 3, tx = t & 7;
        size_t row = ((size_t)b << 16) + (size_t)(wy * 8 + ty) * 256 + (wx * 8 + tx);
        kv[idx] = qkv[row * 540 + 180 + c];
    }
    __syncthreads();

    const int h = tid / 64;
    const int t = tid & 63;
    const int ty = t >> 3, tx = t & 7;
    size_t row = ((size_t)b << 16) + (size_t)(wy * 8 + ty) * 256 + (wx * 8 + tx);

    float2 q2[15];
    const float2* qp = (const float2*)(qkv + row * 540 + h * HDIM);
    const float scale = 0.18257418583505536f;  // 30^-0.5
#pragma unroll
    for (int d = 0; d < 15; d++) {
        float2 qv = qp[d];
        q2[d] = make_float2(qv.x * scale, qv.y * scale);
    }

    const float* br = b_rel + h * 4096 + t * 64;
    float l = 0.f;
    float2 o2[15];
#pragma unroll
    for (int d = 0; d < 15; d++) o2[d] = make_float2(0.f, 0.f);

    for (int j = 0; j < 64; j++) {
        const float2* kj = (const float2*)&kv[j * 360 + h * HDIM];
        float s = br[j];
#pragma unroll
        for (int d = 0; d < 15; d++) {
            float2 kk = kj[d];
            s += q2[d].x * kk.x + q2[d].y * kk.y;
        }
        float p = __expf(s);
        l += p;
        const float2* vj = (const float2*)&kv[j * 360 + 180 + h * HDIM];
#pragma unroll
        for (int d = 0; d < 15; d++) {
            float2 vv = vj[d];
            o2[d].x += p * vv.x;
            o2[d].y += p * vv.y;
        }
    }
    float inv = 1.f / l;
    float* op = out + row * CC + h * HDIM;
#pragma unroll
    for (int d = 0; d < 15; d++) {
        op[2 * d]     = tf32r(o2[d].x * inv);
        op[2 * d + 1] = tf32r(o2[d].y * inv);
    }
}

// ---------------- depthwise 3x3 SAME conv, rolling-y registers ----------------
// grid (256 x, 4 ychunk, BB), block = CD threads (one channel each)
template <int CD, int GELU, int POOL, int ROUND>
__global__ void dwconv_roll(const float* __restrict__ in,
                            const float* __restrict__ k9,
                            float* __restrict__ out,
                            float* __restrict__ pooled) {
    const int c  = threadIdx.x;
    const int x  = blockIdx.x;
    const int y0 = blockIdx.y * 64;
    const int b  = blockIdx.z;
    float w[9];
#pragma unroll
    for (int i = 0; i < 9; i++) w[i] = k9[c * 9 + i];

    const bool xm = (x > 0), xp = (x < WWID - 1);
    const size_t base = ((size_t)b << 16);

    float r0, r1, r2, s0, s1, s2, t0, t1, t2;
    // row y0-1
    if (y0 > 0) {
        size_t p = (base + (size_t)(y0 - 1) * 256 + x) * CD + c;
        r0 = xm ? in[p - CD] : 0.f;  r1 = in[p];  r2 = xp ? in[p + CD] : 0.f;
    } else { r0 = r1 = r2 = 0.f; }
    // row y0
    {
        size_t p = (base + (size_t)y0 * 256 + x) * CD + c;
        s0 = xm ? in[p - CD] : 0.f;  s1 = in[p];  s2 = xp ? in[p + CD] : 0.f;
    }

    float psum = 0.f;
    for (int yy = y0; yy < y0 + 64; yy++) {
        if (yy + 1 < HH) {
            size_t p = (base + (size_t)(yy + 1) * 256 + x) * CD + c;
            t0 = xm ? in[p - CD] : 0.f;  t1 = in[p];  t2 = xp ? in[p + CD] : 0.f;
        } else { t0 = t1 = t2 = 0.f; }
        float acc = r0 * w[0] + r1 * w[1] + r2 * w[2]
                  + s0 * w[3] + s1 * w[4] + s2 * w[5]
                  + t0 * w[6] + t1 * w[7] + t2 * w[8];
        if (GELU) acc = gelu_exact(acc);
        if (POOL) psum += acc;
        if (ROUND) acc = tf32r(acc);
        out[(base + (size_t)yy * 256 + x) * CD + c] = acc;
        r0 = s0; r1 = s1; r2 = s2;
        s0 = t0; s1 = t1; s2 = t2;
    }
    if (POOL) atomicAdd(&pooled[b * CD + c], psum * (1.f / (float)LL));
}

// ---------------- channel gate ----------------
__global__ void gate_kernel(const float* __restrict__ pooled,
                            const float* __restrict__ w1,
                            const float* __restrict__ w2,
                            float* __restrict__ cm) {
    const int b = blockIdx.x;
    const int tid = threadIdx.x;   // 180
    __shared__ float t1[C8];
    if (tid < C8) {
        float s = 0.f;
        for (int c = 0; c < CC; c++) s += pooled[b * CC + c] * w1[tid * CC + c];
        t1[tid] = gelu_exact(s);
    }
    __syncthreads();
    float s = 0.f;
#pragma unroll
    for (int j = 0; j < C8; j++) s += t1[j] * w2[tid * C8 + j];
    cm[b * CC + tid] = 1.f / (1.f + expf(-s));
}

// ---------------- launch ----------------
extern "C" void kernel_launch(void* const* d_in, const int* in_sizes, int n_in,
                              void* d_out, int out_size) {
    const float* x       = (const float*)d_in[0];
    const float* w_qkv   = (const float*)d_in[1];
    const float* b_rel   = (const float*)d_in[2];
    const float* w_proj  = (const float*)d_in[3];
    const float* b_proj  = (const float*)d_in[4];
    const float* conv_dw = (const float*)d_in[5];
    const float* cg_w1   = (const float*)d_in[6];
    const float* cg_w2   = (const float*)d_in[7];
    const float* ffn_w1  = (const float*)d_in[8];
    const float* ffn_dw  = (const float*)d_in[9];
    const float* ffn_w2  = (const float*)d_in[10];
    const float* n1_g    = (const float*)d_in[11];
    const float* n1_b    = (const float*)d_in[12];
    const float* n2_g    = (const float*)d_in[13];
    const float* n2_b    = (const float*)d_in[14];
    float* out = (float*)d_out;

    float *n1, *qkv, *attn, *attnf, *conv, *xmid, *hs, *pooled, *cm, *wr;
    cudaGetSymbolAddress((void**)&n1,    g_n1);
    cudaGetSymbolAddress((void**)&qkv,   g_qkv);
    cudaGetSymbolAddress((void**)&attn,  g_attn);
    cudaGetSymbolAddress((void**)&attnf, g_attnf);
    cudaGetSymbolAddress((void**)&conv,  g_conv);
    cudaGetSymbolAddress((void**)&xmid,  g_xmid);
    cudaGetSymbolAddress((void**)&hs,    g_hs);
    cudaGetSymbolAddress((void**)&pooled, g_pooled);
    cudaGetSymbolAddress((void**)&cm,     g_cm);
    cudaGetSymbolAddress((void**)&wr,     g_wr);

    const int GEMM_SMEM = (2 * 128 * 36 + 2 * 64 * 36) * sizeof(float);  // 55296
    const int ATTN_SMEM = 64 * 360 * sizeof(float);                      // 92160
    cudaFuncSetAttribute(mma_gemm<0>, cudaFuncAttributeMaxDynamicSharedMemorySize, GEMM_SMEM);
    cudaFuncSetAttribute(mma_gemm<1>, cudaFuncAttributeMaxDynamicSharedMemorySize, GEMM_SMEM);
    cudaFuncSetAttribute(mma_gemm<2>, cudaFuncAttributeMaxDynamicSharedMemorySize, GEMM_SMEM);
    cudaFuncSetAttribute(mma_gemm<3>, cudaFuncAttributeMaxDynamicSharedMemorySize, GEMM_SMEM);
    cudaFuncSetAttribute(attn_kernel, cudaFuncAttributeMaxDynamicSharedMemorySize, ATTN_SMEM);

    // 0) round weights to tf32
    roundw_kernel<<<(97200 + 255) / 256, 256>>>(w_qkv,  wr + WR_QKV,  97200);
    roundw_kernel<<<(32400 + 255) / 256, 256>>>(w_proj, wr + WR_PROJ, 32400);
    roundw_kernel<<<(64800 + 255) / 256, 256>>>(ffn_w1, wr + WR_FFN1, 64800);
    roundw_kernel<<<(64800 + 255) / 256, 256>>>(ffn_w2, wr + WR_FFN2, 64800);

    // 1) ln1: x -> n1 (tf32-rounded)
    ln_kernel<<<MROWS / 4, 128>>>(x, n1_g, n1_b, n1);

    // 2) qkv = n1 @ w_qkv^T   (N=540, K=180)
    mma_gemm<0><<<dim3(MROWS / 128, 9), 256, GEMM_SMEM>>>(n1, wr + WR_QKV, nullptr, nullptr, qkv, 540, 180);

    // 3) window attention -> attn (tf32-rounded)
    attn_kernel<<<NWIN, 384, ATTN_SMEM>>>(qkv, b_rel, attn);

    // 4) proj: attnf = attn @ w_proj^T + b_proj
    mma_gemm<1><<<dim3(MROWS / 128, 3), 256, GEMM_SMEM>>>(attn, wr + WR_PROJ, b_proj, nullptr, attnf, 180, 180);

    // 5) conv branch: dwconv(n1)+GELU -> conv, fused mean-pool
    cudaMemsetAsync(pooled, 0, BB * CC * sizeof(float));
    dwconv_roll<CC, 1, 1, 0><<<dim3(WWID, 4, BB), CC>>>(n1, conv_dw, conv, pooled);

    // 6) channel gate -> cm
    gate_kernel<<<BB, CC>>>(pooled, cg_w1, cg_w2, cm);

    // 7) fused residual + ln2: xmid, n2 (n2 into attn buffer, tf32-rounded)
    resid_ln_kernel<<<MROWS / 4, 128>>>(x, attnf, conv, cm, n2_g, n2_b, xmid, attn);

    // 8) ffn1: h = gelu(n2 @ ffn_w1^T) -> qkv buffer
    mma_gemm<2><<<dim3(MROWS / 128, 6), 256, GEMM_SMEM>>>(attn, wr + WR_FFN1, nullptr, nullptr, qkv, 360, 180);

    // 9) ffn dwconv: hs = dwconv(h), tf32-rounded
    dwconv_roll<CFFN, 0, 0, 1><<<dim3(WWID, 4, BB), CFFN>>>(qkv, ffn_dw, hs, nullptr);

    // 10) ffn2 + residual: out = xmid + hs @ ffn_w2^T
    mma_gemm<3><<<dim3(MROWS / 128, 3), 256, GEMM_SMEM>>>(hs, wr + WR_FFN2, nullptr, xmid, out, 180, 360);
}

// round 5
// speedup vs baseline: 3.2581x; 1.0290x over previous
#include <cuda_runtime.h>
#include <cuda_bf16.h>
#include <math.h>
#include <cstdint>

// ---------------- problem constants ----------------
#define BB 2
#define HH 256
#define WWID 256
#define LL 65536          // H*W
#define CC 180
#define NHD 6
#define HDIM 30
#define WSZ 8
#define NWIN 2048         // B * (H/8) * (W/8)
#define CFFN 360
#define C8 22             // 180 // 8
#define MROWS (BB*LL)     // 131072
#define KP1 192           // padded K for K=180
#define KP2 384           // padded K for K=360

// ---------------- scratch (device globals, no allocation) ----------------
__device__ float g_qkv  [(size_t)MROWS*540];   // qkv fp32; reused for h (M x 360)
__device__ float g_attnf[(size_t)MROWS*CC];
__device__ float g_conv [(size_t)MROWS*CC];
__device__ float g_xmid [(size_t)MROWS*CC];
__device__ float g_pooled[BB*CC];
__device__ float g_cm    [BB*CC];
__device__ __nv_bfloat16 g_n1b[(size_t)MROWS*KP1];   // ln1 out (bf16, padded)
__device__ __nv_bfloat16 g_n2b[(size_t)MROWS*KP1];   // attn out, then n2 (bf16, padded)
__device__ __nv_bfloat16 g_hsb[(size_t)MROWS*KP2];   // ffn dwconv out (bf16, padded)
__device__ __nv_bfloat16 g_wb [294912];              // padded bf16 weights

#define WB_QKV  0        // 576 x 192
#define WB_PROJ 110592   // 192 x 192
#define WB_FFN1 147456   // 384 x 192
#define WB_FFN2 221184   // 192 x 384

__device__ __forceinline__ float gelu_exact(float x) {
    return 0.5f * x * (1.0f + erff(x * 0.70710678118654752f));
}

// ---------------- weight convert + pad: src[N][K] fp32 -> dst[NP][KP] bf16 ----------------
__global__ void convw_kernel(const float* __restrict__ src, __nv_bfloat16* __restrict__ dst,
                             int N, int K, int NP, int KP) {
    int i = blockIdx.x * 256 + threadIdx.x;
    if (i < NP * KP) {
        int n = i / KP, k = i - n * KP;
        float v = (n < N && k < K) ? src[n * K + k] : 0.f;
        dst[i] = __float2bfloat16(v);
    }
}

// ---------------- LayerNorm (emits bf16, KP1-padded) ----------------
__global__ void ln_kernel(const float* __restrict__ x,
                          const float* __restrict__ g,
                          const float* __restrict__ b,
                          __nv_bfloat16* __restrict__ out) {
    int row = blockIdx.x * 4 + (threadIdx.x >> 5);
    int lane = threadIdx.x & 31;
    const float* xr = x + (size_t)row * CC;
    float v[6];
    float s = 0.f;
#pragma unroll
    for (int i = 0; i < 6; i++) {
        int c = lane + 32 * i;
        v[i] = (c < CC) ? xr[c] : 0.f;
        s += v[i];
    }
#pragma unroll
    for (int o = 16; o; o >>= 1) s += __shfl_xor_sync(0xffffffffu, s, o);
    float mean = s * (1.f / CC);
    float vs = 0.f;
#pragma unroll
    for (int i = 0; i < 6; i++) {
        int c = lane + 32 * i;
        if (c < CC) { float d = v[i] - mean; vs += d * d; }
    }
#pragma unroll
    for (int o = 16; o; o >>= 1) vs += __shfl_xor_sync(0xffffffffu, vs, o);
    float rstd = rsqrtf(vs * (1.f / CC) + 1e-5f);
    __nv_bfloat16* orow = out + (size_t)row * KP1;
#pragma unroll
    for (int i = 0; i < 6; i++) {
        int c = lane + 32 * i;
        float val = (c < CC) ? (v[i] - mean) * rstd * g[c] + b[c] : 0.f;
        orow[c] = __float2bfloat16(val);
    }
}

// ---------------- fused: xmid = x + attnf*cm + conv; n2 = bf16(LN(xmid)) ----------------
__global__ void resid_ln_kernel(const float* __restrict__ x,
                                const float* __restrict__ attnf,
                                const float* __restrict__ conv,
                                const float* __restrict__ cm,
                                const float* __restrict__ g,
                                const float* __restrict__ b,
                                float* __restrict__ xmid,
                                __nv_bfloat16* __restrict__ n2) {
    int row = blockIdx.x * 4 + (threadIdx.x >> 5);
    int lane = threadIdx.x & 31;
    int bb = row >> 16;
    size_t base = (size_t)row * CC;
    float v[6];
    float s = 0.f;
#pragma unroll
    for (int i = 0; i < 6; i++) {
        int c = lane + 32 * i;
        if (c < CC) {
            float xv = x[base + c] + attnf[base + c] * cm[bb * CC + c] + conv[base + c];
            xmid[base + c] = xv;
            v[i] = xv;
        } else v[i] = 0.f;
        s += v[i];
    }
#pragma unroll
    for (int o = 16; o; o >>= 1) s += __shfl_xor_sync(0xffffffffu, s, o);
    float mean = s * (1.f / CC);
    float vs = 0.f;
#pragma unroll
    for (int i = 0; i < 6; i++) {
        int c = lane + 32 * i;
        if (c < CC) { float d = v[i] - mean; vs += d * d; }
    }
#pragma unroll
    for (int o = 16; o; o >>= 1) vs += __shfl_xor_sync(0xffffffffu, vs, o);
    float rstd = rsqrtf(vs * (1.f / CC) + 1e-5f);
    __nv_bfloat16* orow = n2 + (size_t)row * KP1;
#pragma unroll
    for (int i = 0; i < 6; i++) {
        int c = lane + 32 * i;
        float val = (c < CC) ? (v[i] - mean) * rstd * g[c] + b[c] : 0.f;
        orow[c] = __float2bfloat16(val);
    }
}

// ---------------- bf16 tensor-core GEMM: C = A[MxKP] @ W[NPxKP]^T (+epi) ----------------
// A, W bf16 zero-padded to KP (mult of 32). EPI: 0=none 1=+bias 2=gelu 3=+residual
template <int EPI>
__global__ void __launch_bounds__(256) mma_gemm(const __nv_bfloat16* __restrict__ A,
                                                const __nv_bfloat16* __restrict__ Wt,
                                                const float* __restrict__ bias,
                                                const float* __restrict__ res,
                                                float* __restrict__ Cout,
                                                int N, int KP) {
    extern __shared__ __nv_bfloat16 sm[];
    __nv_bfloat16* As = sm;                       // [2][128][40]
    __nv_bfloat16* Bs = sm + 2 * 128 * 40;        // [2][64][40]
    const int tid  = threadIdx.x;
    const int row0 = blockIdx.x * 128;
    const int col0 = blockIdx.y * 64;
    const int NS   = KP >> 5;
    const int wid  = tid >> 5;
    const int lane = tid & 31;
    const int warpm = wid >> 1;           // 0..3
    const int warpn = wid & 1;            // 0..1
    const int gr = lane >> 2;             // 0..7
    const int cq = lane & 3;              // 0..3

    uint32_t sA = (uint32_t)__cvta_generic_to_shared(As);
    uint32_t sB = (uint32_t)__cvta_generic_to_shared(Bs);

    auto issue = [&](int s) {
        const int k0  = s << 5;
        const int buf = s & 1;
        uint32_t abase = sA + buf * (128 * 40 * 2);
        uint32_t bbase = sB + buf * (64 * 40 * 2);
#pragma unroll
        for (int i = 0; i < 2; i++) {                 // A: 512 16B chunks (8 bf16 each)
            int cid = tid + 256 * i;
            int m = cid >> 2, kc = (cid & 3) << 3;
            const __nv_bfloat16* g = A + (size_t)(row0 + m) * KP + k0 + kc;
            uint32_t sa = abase + (uint32_t)(m * 40 + kc) * 2;
            asm volatile("cp.async.cg.shared.global [%0], [%1], 16;\n"
                         :: "r"(sa), "l"(g));
        }
        {                                             // B: 256 16B chunks
            int n = tid >> 2, kc = (tid & 3) << 3;
            const __nv_bfloat16* g = Wt + (size_t)(col0 + n) * KP + k0 + kc;
            uint32_t sb = bbase + (uint32_t)(n * 40 + kc) * 2;
            asm volatile("cp.async.cg.shared.global [%0], [%1], 16;\n"
                         :: "r"(sb), "l"(g));
        }
        asm volatile("cp.async.commit_group;\n");
    };

    float acc[2][4][4];
#pragma unroll
    for (int a = 0; a < 2; a++)
#pragma unroll
        for (int b = 0; b < 4; b++)
#pragma unroll
            for (int c = 0; c < 4; c++) acc[a][b][c] = 0.f;

    issue(0);
    for (int s = 0; s < NS; s++) {
        if (s + 1 < NS) {
            issue(s + 1);
            asm volatile("cp.async.wait_group 1;\n");
        } else {
            asm volatile("cp.async.wait_group 0;\n");
        }
        __syncthreads();
        const __nv_bfloat16* Ab = As + (s & 1) * (128 * 40);
        const __nv_bfloat16* Bb = Bs + (s & 1) * (64 * 40);
#pragma unroll
        for (int kk = 0; kk < 2; kk++) {              // two k16 sub-steps
            uint32_t afr[2][4], bfr[4][2];
#pragma unroll
            for (int mt = 0; mt < 2; mt++) {
                const __nv_bfloat16* p = Ab + (warpm * 32 + mt * 16 + gr) * 40 + kk * 16 + cq * 2;
                afr[mt][0] = *(const uint32_t*)p;
                afr[mt][1] = *(const uint32_t*)(p + 8 * 40);
                afr[mt][2] = *(const uint32_t*)(p + 8);
                afr[mt][3] = *(const uint32_t*)(p + 8 * 40 + 8);
            }
#pragma unroll
            for (int nt = 0; nt < 4; nt++) {
                const __nv_bfloat16* p = Bb + (warpn * 32 + nt * 8 + gr) * 40 + kk * 16 + cq * 2;
                bfr[nt][0] = *(const uint32_t*)p;
                bfr[nt][1] = *(const uint32_t*)(p + 8);
            }
#pragma unroll
            for (int mt = 0; mt < 2; mt++)
#pragma unroll
                for (int nt = 0; nt < 4; nt++) {
                    asm volatile(
                        "mma.sync.aligned.m16n8k16.row.col.f32.bf16.bf16.f32 "
                        "{%0,%1,%2,%3},{%4,%5,%6,%7},{%8,%9},{%0,%1,%2,%3};\n"
                        : "+f"(acc[mt][nt][0]), "+f"(acc[mt][nt][1]),
                          "+f"(acc[mt][nt][2]), "+f"(acc[mt][nt][3])
                        : "r"(afr[mt][0]), "r"(afr[mt][1]), "r"(afr[mt][2]), "r"(afr[mt][3]),
                          "r"(bfr[nt][0]), "r"(bfr[nt][1]));
                }
        }
        __syncthreads();
    }

#pragma unroll
    for (int mt = 0; mt < 2; mt++) {
        int r0 = row0 + warpm * 32 + mt * 16 + gr;
#pragma unroll
        for (int nt = 0; nt < 4; nt++) {
            int cb = col0 + warpn * 32 + nt * 8 + cq * 2;
            if (cb < N) {
                float v00 = acc[mt][nt][0], v01 = acc[mt][nt][1];
                float v10 = acc[mt][nt][2], v11 = acc[mt][nt][3];
                if (EPI == 1) { float b0 = bias[cb], b1 = bias[cb + 1];
                                v00 += b0; v01 += b1; v10 += b0; v11 += b1; }
                if (EPI == 2) { v00 = gelu_exact(v00); v01 = gelu_exact(v01);
                                v10 = gelu_exact(v10); v11 = gelu_exact(v11); }
                if (EPI == 3) {
                    const float2 r0v = *(const float2*)&res[(size_t)r0 * N + cb];
                    const float2 r1v = *(const float2*)&res[(size_t)(r0 + 8) * N + cb];
                    v00 += r0v.x; v01 += r0v.y; v10 += r1v.x; v11 += r1v.y;
                }
                *(float2*)&Cout[(size_t)r0 * N + cb]       = make_float2(v00, v01);
                *(float2*)&Cout[(size_t)(r0 + 8) * N + cb] = make_float2(v10, v11);
            }
        }
    }
}

// ---------------- window attention (no-max softmax), bf16 padded output ----------------
__global__ void attn_kernel(const float* __restrict__ qkv,
                            const float* __restrict__ b_rel,
                            __nv_bfloat16* __restrict__ out) {
    extern __shared__ float kv[];   // [64][360]: cols 0..179 = K, 180..359 = V
    const int w = blockIdx.x;
    const int b  = w >> 10;
    const int wy = (w & 1023) >> 5;
    const int wx = w & 31;
    const int tid = threadIdx.x;    // 384

    for (int idx = tid; idx < 64 * 360; idx += 384) {
        int t = idx / 360, c = idx - t * 360;
        int ty = t >> 3, tx = t & 7;
        size_t row = ((size_t)b << 16) + (size_t)(wy * 8 + ty) * 256 + (wx * 8 + tx);
        kv[idx] = qkv[row * 540 + 180 + c];
    }
    // zero padding columns 180..191 of output rows for this window
    for (int idx = tid; idx < 64 * 12; idx += 384) {
        int t = idx / 12, c = idx - t * 12;
        int ty = t >> 3, tx = t & 7;
        size_t row = ((size_t)b << 16) + (size_t)(wy * 8 + ty) * 256 + (wx * 8 + tx);
        out[row * KP1 + 180 + c] = __float2bfloat16(0.f);
    }
    __syncthreads();

    const int h = tid / 64;
    const int t = tid & 63;
    const int ty = t >> 3, tx = t & 7;
    size_t row = ((size_t)b << 16) + (size_t)(wy * 8 + ty) * 256 + (wx * 8 + tx);

    float2 q2[15];
    const float2* qp = (const float2*)(qkv + row * 540 + h * HDIM);
    const float scale = 0.18257418583505536f;  // 30^-0.5
#pragma unroll
    for (int d = 0; d < 15; d++) {
        float2 qv = qp[d];
        q2[d] = make_float2(qv.x * scale, qv.y * scale);
    }

    const float* br = b_rel + h * 4096 + t * 64;
    float l = 0.f;
    float2 o2[15];
#pragma unroll
    for (int d = 0; d < 15; d++) o2[d] = make_float2(0.f, 0.f);

    for (int j = 0; j < 64; j++) {
        const float2* kj = (const float2*)&kv[j * 360 + h * HDIM];
        float s = br[j];
#pragma unroll
        for (int d = 0; d < 15; d++) {
            float2 kk = kj[d];
            s += q2[d].x * kk.x + q2[d].y * kk.y;
        }
        float p = __expf(s);
        l += p;
        const float2* vj = (const float2*)&kv[j * 360 + 180 + h * HDIM];
#pragma unroll
        for (int d = 0; d < 15; d++) {
            float2 vv = vj[d];
            o2[d].x += p * vv.x;
            o2[d].y += p * vv.y;
        }
    }
    float inv = 1.f / l;
    __nv_bfloat16* op = out + row * KP1 + h * HDIM;
#pragma unroll
    for (int d = 0; d < 15; d++) {
        op[2 * d]     = __float2bfloat16(o2[d].x * inv);
        op[2 * d + 1] = __float2bfloat16(o2[d].y * inv);
    }
}

// ---------------- depthwise 3x3 SAME conv, rolling-y registers ----------------
// grid (256 x, 4 ychunk, BB), block = CD threads (one channel each)
template <typename Tin, typename Tout, int CD, int INS, int OUTS, int GELU, int POOL>
__global__ void dwconv_roll(const Tin* __restrict__ in,
                            const float* __restrict__ k9,
                            Tout* __restrict__ out,
                            float* __restrict__ pooled) {
    const int c  = threadIdx.x;
    const int x  = blockIdx.x;
    const int y0 = blockIdx.y * 64;
    const int b  = blockIdx.z;
    float w[9];
#pragma unroll
    for (int i = 0; i < 9; i++) w[i] = k9[c * 9 + i];

    const bool xm = (x > 0), xp = (x < WWID - 1);
    const size_t base = ((size_t)b << 16);

    auto ld = [&](size_t p) -> float { return (float)in[p]; };

    float r0, r1, r2, s0, s1, s2, t0, t1, t2;
    if (y0 > 0) {
        size_t p = (base + (size_t)(y0 - 1) * 256 + x) * INS + c;
        r0 = xm ? ld(p - INS) : 0.f;  r1 = ld(p);  r2 = xp ? ld(p + INS) : 0.f;
    } else { r0 = r1 = r2 = 0.f; }
    {
        size_t p = (base + (size_t)y0 * 256 + x) * INS + c;
        s0 = xm ? ld(p - INS) : 0.f;  s1 = ld(p);  s2 = xp ? ld(p + INS) : 0.f;
    }

    float psum = 0.f;
    for (int yy = y0; yy < y0 + 64; yy++) {
        if (yy + 1 < HH) {
            size_t p = (base + (size_t)(yy + 1) * 256 + x) * INS + c;
            t0 = xm ? ld(p - INS) : 0.f;  t1 = ld(p);  t2 = xp ? ld(p + INS) : 0.f;
        } else { t0 = t1 = t2 = 0.f; }
        float acc = r0 * w[0] + r1 * w[1] + r2 * w[2]
                  + s0 * w[3] + s1 * w[4] + s2 * w[5]
                  + t0 * w[6] + t1 * w[7] + t2 * w[8];
        if (GELU) acc = gelu_exact(acc);
        if (POOL) psum += acc;
        size_t op = (base + (size_t)yy * 256 + x) * OUTS;
        out[op + c] = (Tout)acc;
        if (OUTS > CD && c < OUTS - CD) out[op + CD + c] = (Tout)0.f;
        r0 = s0; r1 = s1; r2 = s2;
        s0 = t0; s1 = t1; s2 = t2;
    }
    if (POOL) atomicAdd(&pooled[b * CD + c], psum * (1.f / (float)LL));
}

// ---------------- channel gate ----------------
__global__ void gate_kernel(const float* __restrict__ pooled,
                            const float* __restrict__ w1,
                            const float* __restrict__ w2,
                            float* __restrict__ cm) {
    const int b = blockIdx.x;
    const int tid = threadIdx.x;   // 180
    __shared__ float t1[C8];
    if (tid < C8) {
        float s = 0.f;
        for (int c = 0; c < CC; c++) s += pooled[b * CC + c] * w1[tid * CC + c];
        t1[tid] = gelu_exact(s);
    }
    __syncthreads();
    float s = 0.f;
#pragma unroll
    for (int j = 0; j < C8; j++) s += t1[j] * w2[tid * C8 + j];
    cm[b * CC + tid] = 1.f / (1.f + expf(-s));
}

// ---------------- launch ----------------
extern "C" void kernel_launch(void* const* d_in, const int* in_sizes, int n_in,
                              void* d_out, int out_size) {
    const float* x       = (const float*)d_in[0];
    const float* w_qkv   = (const float*)d_in[1];
    const float* b_rel   = (const float*)d_in[2];
    const float* w_proj  = (const float*)d_in[3];
    const float* b_proj  = (const float*)d_in[4];
    const float* conv_dw = (const float*)d_in[5];
    const float* cg_w1   = (const float*)d_in[6];
    const float* cg_w2   = (const float*)d_in[7];
    const float* ffn_w1  = (const float*)d_in[8];
    const float* ffn_dw  = (const float*)d_in[9];
    const float* ffn_w2  = (const float*)d_in[10];
    const float* n1_g    = (const float*)d_in[11];
    const float* n1_b    = (const float*)d_in[12];
    const float* n2_g    = (const float*)d_in[13];
    const float* n2_b    = (const float*)d_in[14];
    float* out = (float*)d_out;

    float *qkv, *attnf, *conv, *xmid, *pooled, *cm;
    __nv_bfloat16 *n1b, *n2b, *hsb, *wb;
    cudaGetSymbolAddress((void**)&qkv,   g_qkv);
    cudaGetSymbolAddress((void**)&attnf, g_attnf);
    cudaGetSymbolAddress((void**)&conv,  g_conv);
    cudaGetSymbolAddress((void**)&xmid,  g_xmid);
    cudaGetSymbolAddress((void**)&pooled, g_pooled);
    cudaGetSymbolAddress((void**)&cm,     g_cm);
    cudaGetSymbolAddress((void**)&n1b,   g_n1b);
    cudaGetSymbolAddress((void**)&n2b,   g_n2b);
    cudaGetSymbolAddress((void**)&hsb,   g_hsb);
    cudaGetSymbolAddress((void**)&wb,    g_wb);

    const int GEMM_SMEM = (2 * 128 * 40 + 2 * 64 * 40) * sizeof(__nv_bfloat16);  // 30720
    const int ATTN_SMEM = 64 * 360 * sizeof(float);                              // 92160
    cudaFuncSetAttribute(mma_gemm<0>, cudaFuncAttributeMaxDynamicSharedMemorySize, GEMM_SMEM);
    cudaFuncSetAttribute(mma_gemm<1>, cudaFuncAttributeMaxDynamicSharedMemorySize, GEMM_SMEM);
    cudaFuncSetAttribute(mma_gemm<2>, cudaFuncAttributeMaxDynamicSharedMemorySize, GEMM_SMEM);
    cudaFuncSetAttribute(mma_gemm<3>, cudaFuncAttributeMaxDynamicSharedMemorySize, GEMM_SMEM);
    cudaFuncSetAttribute(attn_kernel, cudaFuncAttributeMaxDynamicSharedMemorySize, ATTN_SMEM);

    // 0) convert + pad weights to bf16
    convw_kernel<<<(576 * 192 + 255) / 256, 256>>>(w_qkv,  wb + WB_QKV,  540, 180, 576, 192);
    convw_kernel<<<(192 * 192 + 255) / 256, 256>>>(w_proj, wb + WB_PROJ, 180, 180, 192, 192);
    convw_kernel<<<(384 * 192 + 255) / 256, 256>>>(ffn_w1, wb + WB_FFN1, 360, 180, 384, 192);
    convw_kernel<<<(192 * 384 + 255) / 256, 256>>>(ffn_w2, wb + WB_FFN2, 180, 360, 192, 384);

    // 1) ln1: x -> n1b (bf16, padded)
    ln_kernel<<<MROWS / 4, 128>>>(x, n1_g, n1_b, n1b);

    // 2) qkv = n1 @ w_qkv^T   (N=540, KP=192)
    mma_gemm<0><<<dim3(MROWS / 128, 9), 256, GEMM_SMEM>>>(n1b, wb + WB_QKV, nullptr, nullptr, qkv, 540, 192);

    // 3) window attention -> n2b (bf16, padded)
    attn_kernel<<<NWIN, 384, ATTN_SMEM>>>(qkv, b_rel, n2b);

    // 4) proj: attnf = attn @ w_proj^T + b_proj
    mma_gemm<1><<<dim3(MROWS / 128, 3), 256, GEMM_SMEM>>>(n2b, wb + WB_PROJ, b_proj, nullptr, attnf, 180, 192);

    // 5) conv branch: dwconv(n1b)+GELU -> conv (fp32), fused mean-pool
    cudaMemsetAsync(pooled, 0, BB * CC * sizeof(float));
    dwconv_roll<__nv_bfloat16, float, CC, KP1, CC, 1, 1><<<dim3(WWID, 4, BB), CC>>>(n1b, conv_dw, conv, pooled);

    // 6) channel gate -> cm
    gate_kernel<<<BB, CC>>>(pooled, cg_w1, cg_w2, cm);

    // 7) fused residual + ln2: xmid (fp32), n2 -> n2b (bf16)
    resid_ln_kernel<<<MROWS / 4, 128>>>(x, attnf, conv, cm, n2_g, n2_b, xmid, n2b);

    // 8) ffn1: h = gelu(n2 @ ffn_w1^T) -> qkv buffer (fp32, stride 360)
    mma_gemm<2><<<dim3(MROWS / 128, 6), 256, GEMM_SMEM>>>(n2b, wb + WB_FFN1, nullptr, nullptr, qkv, 360, 192);

    // 9) ffn dwconv: hsb = dwconv(h) (bf16, padded to 384)
    dwconv_roll<float, __nv_bfloat16, CFFN, CFFN, KP2, 0, 0><<<dim3(WWID, 4, BB), CFFN>>>(qkv, ffn_dw, hsb, nullptr);

    // 10) ffn2 + residual: out = xmid + hsb @ ffn_w2^T
    mma_gemm<3><<<dim3(MROWS / 128, 3), 256, GEMM_SMEM>>>(hsb, wb + WB_FFN2, nullptr, xmid, out, 180, 384);
}

// round 6
// speedup vs baseline: 3.6444x; 1.1186x over previous
#include <cuda_runtime.h>
#include <cuda_bf16.h>
#include <math.h>
#include <cstdint>

using bf16 = __nv_bfloat16;

// ---------------- problem constants ----------------
#define BB 2
#define HH 256
#define WWID 256
#define LL 65536          // H*W
#define CC 180
#define NHD 6
#define HDIM 30
#define NWIN 2048         // B * (H/8) * (W/8)
#define CFFN 360
#define C8 22             // 180 // 8
#define MROWS (BB*LL)     // 131072
#define KP1 192           // padded K for K=180
#define KP2 384           // padded K for K=360

// ---------------- scratch (device globals, no allocation) ----------------
__device__ bf16  g_qkvb [(size_t)MROWS*540];   // qkv bf16; reused for h (stride 384)
__device__ float g_attnf[(size_t)MROWS*CC];
__device__ float g_conv [(size_t)MROWS*CC];
__device__ float g_xmid [(size_t)MROWS*CC];
__device__ float g_pooled[BB*CC];
__device__ float g_cm    [BB*CC];
__device__ bf16  g_n1b[(size_t)MROWS*KP1];     // ln1 out (bf16, padded)
__device__ bf16  g_n2b[(size_t)MROWS*KP1];     // attn out, then n2 (bf16, padded)
__device__ bf16  g_hsb[(size_t)MROWS*KP2];     // ffn dwconv out (bf16, padded)
__device__ bf16  g_wb [294912];                // padded bf16 weights

#define WB_QKV  0        // 576 x 192
#define WB_PROJ 110592   // 192 x 192
#define WB_FFN1 147456   // 384 x 192
#define WB_FFN2 221184   // 192 x 384

__device__ __forceinline__ float gelu_exact(float x) {
    return 0.5f * x * (1.0f + erff(x * 0.70710678118654752f));
}

// ---------------- weight convert + pad: src[N][K] fp32 -> dst[NP][KP] bf16 ----------------
__global__ void convw_kernel(const float* __restrict__ src, bf16* __restrict__ dst,
                             int N, int K, int NP, int KP) {
    int i = blockIdx.x * 256 + threadIdx.x;
    if (i < NP * KP) {
        int n = i / KP, k = i - n * KP;
        float v = (n < N && k < K) ? src[n * K + k] : 0.f;
        dst[i] = __float2bfloat16(v);
    }
}

// ---------------- LayerNorm (emits bf16, KP1-padded) ----------------
__global__ void ln_kernel(const float* __restrict__ x,
                          const float* __restrict__ g,
                          const float* __restrict__ b,
                          bf16* __restrict__ out) {
    int row = blockIdx.x * 4 + (threadIdx.x >> 5);
    int lane = threadIdx.x & 31;
    const float* xr = x + (size_t)row * CC;
    float v[6];
    float s = 0.f;
#pragma unroll
    for (int i = 0; i < 6; i++) {
        int c = lane + 32 * i;
        v[i] = (c < CC) ? xr[c] : 0.f;
        s += v[i];
    }
#pragma unroll
    for (int o = 16; o; o >>= 1) s += __shfl_xor_sync(0xffffffffu, s, o);
    float mean = s * (1.f / CC);
    float vs = 0.f;
#pragma unroll
    for (int i = 0; i < 6; i++) {
        int c = lane + 32 * i;
        if (c < CC) { float d = v[i] - mean; vs += d * d; }
    }
#pragma unroll
    for (int o = 16; o; o >>= 1) vs += __shfl_xor_sync(0xffffffffu, vs, o);
    float rstd = rsqrtf(vs * (1.f / CC) + 1e-5f);
    bf16* orow = out + (size_t)row * KP1;
#pragma unroll
    for (int i = 0; i < 6; i++) {
        int c = lane + 32 * i;
        float val = (c < CC) ? (v[i] - mean) * rstd * g[c] + b[c] : 0.f;
        orow[c] = __float2bfloat16(val);
    }
}

// ---------------- fused: xmid = x + attnf*cm + conv; n2 = bf16(LN(xmid)) ----------------
__global__ void resid_ln_kernel(const float* __restrict__ x,
                                const float* __restrict__ attnf,
                                const float* __restrict__ conv,
                                const float* __restrict__ cm,
                                const float* __restrict__ g,
                                const float* __restrict__ b,
                                float* __restrict__ xmid,
                                bf16* __restrict__ n2) {
    int row = blockIdx.x * 4 + (threadIdx.x >> 5);
    int lane = threadIdx.x & 31;
    int bb = row >> 16;
    size_t base = (size_t)row * CC;
    float v[6];
    float s = 0.f;
#pragma unroll
    for (int i = 0; i < 6; i++) {
        int c = lane + 32 * i;
        if (c < CC) {
            float xv = x[base + c] + attnf[base + c] * cm[bb * CC + c] + conv[base + c];
            xmid[base + c] = xv;
            v[i] = xv;
        } else v[i] = 0.f;
        s += v[i];
    }
#pragma unroll
    for (int o = 16; o; o >>= 1) s += __shfl_xor_sync(0xffffffffu, s, o);
    float mean = s * (1.f / CC);
    float vs = 0.f;
#pragma unroll
    for (int i = 0; i < 6; i++) {
        int c = lane + 32 * i;
        if (c < CC) { float d = v[i] - mean; vs += d * d; }
    }
#pragma unroll
    for (int o = 16; o; o >>= 1) vs += __shfl_xor_sync(0xffffffffu, vs, o);
    float rstd = rsqrtf(vs * (1.f / CC) + 1e-5f);
    bf16* orow = n2 + (size_t)row * KP1;
#pragma unroll
    for (int i = 0; i < 6; i++) {
        int c = lane + 32 * i;
        float val = (c < CC) ? (v[i] - mean) * rstd * g[c] + b[c] : 0.f;
        orow[c] = __float2bfloat16(val);
    }
}

// ======== A-resident persistent GEMM: A[128xKP] stays in smem, loop n-tiles ========
// EPI: 0=none 1=+bias 2=gelu ; OBF: 1 -> bf16 output (stride OS), 0 -> fp32 output
template <int EPI, int OBF>
__global__ void __launch_bounds__(256) mma_gemm_p(const bf16* __restrict__ A,
                                                  const bf16* __restrict__ Wt,
                                                  const float* __restrict__ bias,
                                                  float* __restrict__ Cf,
                                                  bf16* __restrict__ Cb,
                                                  int N, int KP, int OS, int NT) {
    extern __shared__ bf16 sm[];
    const int AST = KP + 8;               // row stride (bf16)
    bf16* As = sm;                        // [128][AST]
    bf16* Bs = sm + 128 * AST;            // [2][64][AST]
    const int tid  = threadIdx.x;
    const int row0 = blockIdx.x * 128;
    const int wid  = tid >> 5;
    const int lane = tid & 31;
    const int warpm = wid >> 1;
    const int warpn = wid & 1;
    const int gr = lane >> 2;
    const int cq = lane & 3;
    const int NS = KP >> 4;               // k16 steps
    const int KC = KP >> 3;               // 16B chunks per row

    uint32_t sA = (uint32_t)__cvta_generic_to_shared(As);
    uint32_t sB = (uint32_t)__cvta_generic_to_shared(Bs);

    // load all of A (once)
    for (int cid = tid; cid < 128 * KC; cid += 256) {
        int m = cid / KC, kc = (cid - m * KC) << 3;
        const bf16* g = A + (size_t)(row0 + m) * KP + kc;
        uint32_t sa = sA + (uint32_t)(m * AST + kc) * 2;
        asm volatile("cp.async.cg.shared.global [%0], [%1], 16;\n" :: "r"(sa), "l"(g));
    }
    auto issueB = [&](int t) {
        uint32_t bbase = sB + (t & 1) * (64 * AST * 2);
        const bf16* wt0 = Wt + (size_t)(t * 64) * KP;
        for (int cid = tid; cid < 64 * KC; cid += 256) {
            int n = cid / KC, kc = (cid - n * KC) << 3;
            uint32_t sb = bbase + (uint32_t)(n * AST + kc) * 2;
            asm volatile("cp.async.cg.shared.global [%0], [%1], 16;\n"
                         :: "r"(sb), "l"(wt0 + (size_t)n * KP + kc));
        }
        asm volatile("cp.async.commit_group;\n");
    };

    issueB(0);   // group 0 = A + B0

    for (int t = 0; t < NT; t++) {
        if (t + 1 < NT) { issueB(t + 1); asm volatile("cp.async.wait_group 1;\n"); }
        else            { asm volatile("cp.async.wait_group 0;\n"); }
        __syncthreads();

        float acc[2][4][4];
#pragma unroll
        for (int a = 0; a < 2; a++)
#pragma unroll
            for (int b = 0; b < 4; b++)
#pragma unroll
                for (int c = 0; c < 4; c++) acc[a][b][c] = 0.f;

        const bf16* Bb = Bs + (t & 1) * (64 * AST);
        for (int ks = 0; ks < NS; ks++) {
            uint32_t afr[2][4], bfr[4][2];
#pragma unroll
            for (int mt = 0; mt < 2; mt++) {
                const bf16* p = As + (warpm * 32 + mt * 16 + gr) * AST + ks * 16 + cq * 2;
                afr[mt][0] = *(const uint32_t*)p;
                afr[mt][1] = *(const uint32_t*)(p + 8 * AST);
                afr[mt][2] = *(const uint32_t*)(p + 8);
                afr[mt][3] = *(const uint32_t*)(p + 8 * AST + 8);
            }
#pragma unroll
            for (int nt = 0; nt < 4; nt++) {
                const bf16* p = Bb + (warpn * 32 + nt * 8 + gr) * AST + ks * 16 + cq * 2;
                bfr[nt][0] = *(const uint32_t*)p;
                bfr[nt][1] = *(const uint32_t*)(p + 8);
            }
#pragma unroll
            for (int mt = 0; mt < 2; mt++)
#pragma unroll
                for (int nt = 0; nt < 4; nt++) {
                    asm volatile(
                        "mma.sync.aligned.m16n8k16.row.col.f32.bf16.bf16.f32 "
                        "{%0,%1,%2,%3},{%4,%5,%6,%7},{%8,%9},{%0,%1,%2,%3};\n"
                        : "+f"(acc[mt][nt][0]), "+f"(acc[mt][nt][1]),
                          "+f"(acc[mt][nt][2]), "+f"(acc[mt][nt][3])
                        : "r"(afr[mt][0]), "r"(afr[mt][1]), "r"(afr[mt][2]), "r"(afr[mt][3]),
                          "r"(bfr[nt][0]), "r"(bfr[nt][1]));
                }
        }

        const int col0 = t * 64;
#pragma unroll
        for (int mt = 0; mt < 2; mt++) {
            int r0 = row0 + warpm * 32 + mt * 16 + gr;
#pragma unroll
            for (int nt = 0; nt < 4; nt++) {
                int cb = col0 + warpn * 32 + nt * 8 + cq * 2;
                if (cb < N) {
                    float v00 = acc[mt][nt][0], v01 = acc[mt][nt][1];
                    float v10 = acc[mt][nt][2], v11 = acc[mt][nt][3];
                    if (EPI == 1) { float b0 = bias[cb], b1 = bias[cb + 1];
                                    v00 += b0; v01 += b1; v10 += b0; v11 += b1; }
                    if (EPI == 2) { v00 = gelu_exact(v00); v01 = gelu_exact(v01);
                                    v10 = gelu_exact(v10); v11 = gelu_exact(v11); }
                    if (OBF) {
                        __nv_bfloat162 p0, p1;
                        p0.x = __float2bfloat16(v00); p0.y = __float2bfloat16(v01);
                        p1.x = __float2bfloat16(v10); p1.y = __float2bfloat16(v11);
                        *(__nv_bfloat162*)&Cb[(size_t)r0 * OS + cb]       = p0;
                        *(__nv_bfloat162*)&Cb[(size_t)(r0 + 8) * OS + cb] = p1;
                    } else {
                        *(float2*)&Cf[(size_t)r0 * OS + cb]       = make_float2(v00, v01);
                        *(float2*)&Cf[(size_t)(r0 + 8) * OS + cb] = make_float2(v10, v11);
                    }
                }
            }
        }
        __syncthreads();
    }
}

// ======== pipelined GEMM (for KP=384 ffn2): C = A @ W^T + residual ========
__global__ void __launch_bounds__(256) mma_gemm_res(const bf16* __restrict__ A,
                                                    const bf16* __restrict__ Wt,
                                                    const float* __restrict__ res,
                                                    float* __restrict__ Cout,
                                                    int N, int KP) {
    extern __shared__ bf16 sm[];
    bf16* As = sm;                       // [2][128][40]
    bf16* Bs = sm + 2 * 128 * 40;        // [2][64][40]
    const int tid  = threadIdx.x;
    const int row0 = blockIdx.x * 128;
    const int col0 = blockIdx.y * 64;
    const int NS   = KP >> 5;
    const int wid  = tid >> 5;
    const int lane = tid & 31;
    const int warpm = wid >> 1;
    const int warpn = wid & 1;
    const int gr = lane >> 2;
    const int cq = lane & 3;

    uint32_t sA = (uint32_t)__cvta_generic_to_shared(As);
    uint32_t sB = (uint32_t)__cvta_generic_to_shared(Bs);

    auto issue = [&](int s) {
        const int k0  = s << 5;
        const int buf = s & 1;
        uint32_t abase = sA + buf * (128 * 40 * 2);
        uint32_t bbase = sB + buf * (64 * 40 * 2);
#pragma unroll
        for (int i = 0; i < 2; i++) {
            int cid = tid + 256 * i;
            int m = cid >> 2, kc = (cid & 3) << 3;
            const bf16* g = A + (size_t)(row0 + m) * KP + k0 + kc;
            uint32_t sa = abase + (uint32_t)(m * 40 + kc) * 2;
            asm volatile("cp.async.cg.shared.global [%0], [%1], 16;\n" :: "r"(sa), "l"(g));
        }
        {
            int n = tid >> 2, kc = (tid & 3) << 3;
            const bf16* g = Wt + (size_t)(col0 + n) * KP + k0 + kc;
            uint32_t sb = bbase + (uint32_t)(n * 40 + kc) * 2;
            asm volatile("cp.async.cg.shared.global [%0], [%1], 16;\n" :: "r"(sb), "l"(g));
        }
        asm volatile("cp.async.commit_group;\n");
    };

    float acc[2][4][4];
#pragma unroll
    for (int a = 0; a < 2; a++)
#pragma unroll
        for (int b = 0; b < 4; b++)
#pragma unroll
            for (int c = 0; c < 4; c++) acc[a][b][c] = 0.f;

    issue(0);
    for (int s = 0; s < NS; s++) {
        if (s + 1 < NS) { issue(s + 1); asm volatile("cp.async.wait_group 1;\n"); }
        else            { asm volatile("cp.async.wait_group 0;\n"); }
        __syncthreads();
        const bf16* Ab = As + (s & 1) * (128 * 40);
        const bf16* Bb = Bs + (s & 1) * (64 * 40);
#pragma unroll
        for (int kk = 0; kk < 2; kk++) {
            uint32_t afr[2][4], bfr[4][2];
#pragma unroll
            for (int mt = 0; mt < 2; mt++) {
                const bf16* p = Ab + (warpm * 32 + mt * 16 + gr) * 40 + kk * 16 + cq * 2;
                afr[mt][0] = *(const uint32_t*)p;
                afr[mt][1] = *(const uint32_t*)(p + 8 * 40);
                afr[mt][2] = *(const uint32_t*)(p + 8);
                afr[mt][3] = *(const uint32_t*)(p + 8 * 40 + 8);
            }
#pragma unroll
            for (int nt = 0; nt < 4; nt++) {
                const bf16* p = Bb + (warpn * 32 + nt * 8 + gr) * 40 + kk * 16 + cq * 2;
                bfr[nt][0] = *(const uint32_t*)p;
                bfr[nt][1] = *(const uint32_t*)(p + 8);
            }
#pragma unroll
            for (int mt = 0; mt < 2; mt++)
#pragma unroll
                for (int nt = 0; nt < 4; nt++) {
                    asm volatile(
                        "mma.sync.aligned.m16n8k16.row.col.f32.bf16.bf16.f32 "
                        "{%0,%1,%2,%3},{%4,%5,%6,%7},{%8,%9},{%0,%1,%2,%3};\n"
                        : "+f"(acc[mt][nt][0]), "+f"(acc[mt][nt][1]),
                          "+f"(acc[mt][nt][2]), "+f"(acc[mt][nt][3])
                        : "r"(afr[mt][0]), "r"(afr[mt][1]), "r"(afr[mt][2]), "r"(afr[mt][3]),
                          "r"(bfr[nt][0]), "r"(bfr[nt][1]));
                }
        }
        __syncthreads();
    }

#pragma unroll
    for (int mt = 0; mt < 2; mt++) {
        int r0 = row0 + warpm * 32 + mt * 16 + gr;
#pragma unroll
        for (int nt = 0; nt < 4; nt++) {
            int cb = col0 + warpn * 32 + nt * 8 + cq * 2;
            if (cb < N) {
                const float2 r0v = *(const float2*)&res[(size_t)r0 * N + cb];
                const float2 r1v = *(const float2*)&res[(size_t)(r0 + 8) * N + cb];
                *(float2*)&Cout[(size_t)r0 * N + cb] =
                    make_float2(acc[mt][nt][0] + r0v.x, acc[mt][nt][1] + r0v.y);
                *(float2*)&Cout[(size_t)(r0 + 8) * N + cb] =
                    make_float2(acc[mt][nt][2] + r1v.x, acc[mt][nt][3] + r1v.y);
            }
        }
    }
}

// ---------------- window attention (bf16 qkv input, no-max softmax) ----------------
__global__ void attn_kernel(const bf16* __restrict__ qkv,
                            const float* __restrict__ b_rel,
                            bf16* __restrict__ out) {
    extern __shared__ float kv[];   // [64][360]: cols 0..179 = K, 180..359 = V
    const int w = blockIdx.x;
    const int b  = w >> 10;
    const int wy = (w & 1023) >> 5;
    const int wx = w & 31;
    const int tid = threadIdx.x;    // 384

    for (int idx = tid; idx < 64 * 180; idx += 384) {
        int t = idx / 180, c2 = idx - t * 180;
        int ty = t >> 3, tx = t & 7;
        size_t row = ((size_t)b << 16) + (size_t)(wy * 8 + ty) * 256 + (wx * 8 + tx);
        __nv_bfloat162 v = *(const __nv_bfloat162*)&qkv[row * 540 + 180 + 2 * c2];
        kv[t * 360 + 2 * c2]     = __bfloat162float(v.x);
        kv[t * 360 + 2 * c2 + 1] = __bfloat162float(v.y);
    }
    // zero padding columns 180..191 of output rows for this window
    for (int idx = tid; idx < 64 * 12; idx += 384) {
        int t = idx / 12, c = idx - t * 12;
        int ty = t >> 3, tx = t & 7;
        size_t row = ((size_t)b << 16) + (size_t)(wy * 8 + ty) * 256 + (wx * 8 + tx);
        out[row * KP1 + 180 + c] = __float2bfloat16(0.f);
    }
    __syncthreads();

    const int h = tid / 64;
    const int t = tid & 63;
    const int ty = t >> 3, tx = t & 7;
    size_t row = ((size_t)b << 16) + (size_t)(wy * 8 + ty) * 256 + (wx * 8 + tx);

    float2 q2[15];
    const __nv_bfloat162* qp = (const __nv_bfloat162*)(qkv + row * 540 + h * HDIM);
    const float scale = 0.18257418583505536f;  // 30^-0.5
#pragma unroll
    for (int d = 0; d < 15; d++) {
        __nv_bfloat162 qv = qp[d];
        q2[d] = make_float2(__bfloat162float(qv.x) * scale, __bfloat162float(qv.y) * scale);
    }

    const float* br = b_rel + h * 4096 + t * 64;
    float l = 0.f;
    float2 o2[15];
#pragma unroll
    for (int d = 0; d < 15; d++) o2[d] = make_float2(0.f, 0.f);

    for (int j = 0; j < 64; j++) {
        const float2* kj = (const float2*)&kv[j * 360 + h * HDIM];
        float s = br[j];
#pragma unroll
        for (int d = 0; d < 15; d++) {
            float2 kk = kj[d];
            s += q2[d].x * kk.x + q2[d].y * kk.y;
        }
        float p = __expf(s);
        l += p;
        const float2* vj = (const float2*)&kv[j * 360 + 180 + h * HDIM];
#pragma unroll
        for (int d = 0; d < 15; d++) {
            float2 vv = vj[d];
            o2[d].x += p * vv.x;
            o2[d].y += p * vv.y;
        }
    }
    float inv = 1.f / l;
    bf16* op = out + row * KP1 + h * HDIM;
#pragma unroll
    for (int d = 0; d < 15; d++) {
        op[2 * d]     = __float2bfloat16(o2[d].x * inv);
        op[2 * d + 1] = __float2bfloat16(o2[d].y * inv);
    }
}

// ---------------- depthwise 3x3 SAME conv, x-tiled (TX) + rolling-y ----------------
// grid (WWID/TX, 4, BB), block = CD threads (one channel each)
template <typename Tin, typename Tout, int CD, int INS, int OUTS, int GELU, int POOL, int TX>
__global__ void dwconv_tile(const Tin* __restrict__ in,
                            const float* __restrict__ k9,
                            Tout* __restrict__ out,
                            float* __restrict__ pooled) {
    const int c  = threadIdx.x;
    const int x0 = blockIdx.x * TX;
    const int y0 = blockIdx.y * 64;
    const int b  = blockIdx.z;
    float w[9];
#pragma unroll
    for (int i = 0; i < 9; i++) w[i] = k9[c * 9 + i];

    const size_t base = ((size_t)b << 16);
    float r[TX + 2], s[TX + 2], t[TX + 2];

    auto loadrow = [&](int yy, float* dst) {
#pragma unroll
        for (int i = 0; i < TX + 2; i++) {
            int xx = x0 - 1 + i;
            dst[i] = (xx >= 0 && xx < WWID)
                     ? (float)in[(base + (size_t)yy * 256 + xx) * INS + c] : 0.f;
        }
    };

    if (y0 > 0) loadrow(y0 - 1, r);
    else {
#pragma unroll
        for (int i = 0; i < TX + 2; i++) r[i] = 0.f;
    }
    loadrow(y0, s);

    float psum = 0.f;
    for (int yy = y0; yy < y0 + 64; yy++) {
        if (yy + 1 < HH) loadrow(yy + 1, t);
        else {
#pragma unroll
            for (int i = 0; i < TX + 2; i++) t[i] = 0.f;
        }
#pragma unroll
        for (int j = 0; j < TX; j++) {
            float acc = r[j] * w[0] + r[j + 1] * w[1] + r[j + 2] * w[2]
                      + s[j] * w[3] + s[j + 1] * w[4] + s[j + 2] * w[5]
                      + t[j] * w[6] + t[j + 1] * w[7] + t[j + 2] * w[8];
            if (GELU) acc = gelu_exact(acc);
            if (POOL) psum += acc;
            size_t op = (base + (size_t)yy * 256 + x0 + j) * OUTS;
            out[op + c] = (Tout)acc;
            if (OUTS > CD && c < OUTS - CD) out[op + CD + c] = (Tout)0.f;
        }
#pragma unroll
        for (int i = 0; i < TX + 2; i++) { r[i] = s[i]; s[i] = t[i]; }
    }
    if (POOL) atomicAdd(&pooled[b * CD + c], psum * (1.f / (float)LL));
}

// ---------------- channel gate ----------------
__global__ void gate_kernel(const float* __restrict__ pooled,
                            const float* __restrict__ w1,
                            const float* __restrict__ w2,
                            float* __restrict__ cm) {
    const int b = blockIdx.x;
    const int tid = threadIdx.x;   // 180
    __shared__ float t1[C8];
    if (tid < C8) {
        float s = 0.f;
        for (int c = 0; c < CC; c++) s += pooled[b * CC + c] * w1[tid * CC + c];
        t1[tid] = gelu_exact(s);
    }
    __syncthreads();
    float s = 0.f;
#pragma unroll
    for (int j = 0; j < C8; j++) s += t1[j] * w2[tid * C8 + j];
    cm[b * CC + tid] = 1.f / (1.f + expf(-s));
}

// ---------------- launch ----------------
extern "C" void kernel_launch(void* const* d_in, const int* in_sizes, int n_in,
                              void* d_out, int out_size) {
    const float* x       = (const float*)d_in[0];
    const float* w_qkv   = (const float*)d_in[1];
    const float* b_rel   = (const float*)d_in[2];
    const float* w_proj  = (const float*)d_in[3];
    const float* b_proj  = (const float*)d_in[4];
    const float* conv_dw = (const float*)d_in[5];
    const float* cg_w1   = (const float*)d_in[6];
    const float* cg_w2   = (const float*)d_in[7];
    const float* ffn_w1  = (const float*)d_in[8];
    const float* ffn_dw  = (const float*)d_in[9];
    const float* ffn_w2  = (const float*)d_in[10];
    const float* n1_g    = (const float*)d_in[11];
    const float* n1_b    = (const float*)d_in[12];
    const float* n2_g    = (const float*)d_in[13];
    const float* n2_b    = (const float*)d_in[14];
    float* out = (float*)d_out;

    float *attnf, *conv, *xmid, *pooled, *cm;
    bf16 *qkvb, *n1b, *n2b, *hsb, *wb;
    cudaGetSymbolAddress((void**)&qkvb,  g_qkvb);
    cudaGetSymbolAddress((void**)&attnf, g_attnf);
    cudaGetSymbolAddress((void**)&conv,  g_conv);
    cudaGetSymbolAddress((void**)&xmid,  g_xmid);
    cudaGetSymbolAddress((void**)&pooled, g_pooled);
    cudaGetSymbolAddress((void**)&cm,     g_cm);
    cudaGetSymbolAddress((void**)&n1b,   g_n1b);
    cudaGetSymbolAddress((void**)&n2b,   g_n2b);
    cudaGetSymbolAddress((void**)&hsb,   g_hsb);
    cudaGetSymbolAddress((void**)&wb,    g_wb);

    const int PSMEM1 = (128 * (KP1 + 8) + 2 * 64 * (KP1 + 8)) * (int)sizeof(bf16); // 102400
    const int PIPE_SMEM = (2 * 128 * 40 + 2 * 64 * 40) * (int)sizeof(bf16);        // 30720
    const int ATTN_SMEM = 64 * 360 * (int)sizeof(float);                           // 92160
    cudaFuncSetAttribute((const void*)mma_gemm_p<0,1>, cudaFuncAttributeMaxDynamicSharedMemorySize, PSMEM1);
    cudaFuncSetAttribute((const void*)mma_gemm_p<1,0>, cudaFuncAttributeMaxDynamicSharedMemorySize, PSMEM1);
    cudaFuncSetAttribute((const void*)mma_gemm_p<2,1>, cudaFuncAttributeMaxDynamicSharedMemorySize, PSMEM1);
    cudaFuncSetAttribute((const void*)mma_gemm_res,    cudaFuncAttributeMaxDynamicSharedMemorySize, PIPE_SMEM);
    cudaFuncSetAttribute((const void*)attn_kernel,     cudaFuncAttributeMaxDynamicSharedMemorySize, ATTN_SMEM);

    // 0) convert + pad weights to bf16
    convw_kernel<<<(576 * 192 + 255) / 256, 256>>>(w_qkv,  wb + WB_QKV,  540, 180, 576, 192);
    convw_kernel<<<(192 * 192 + 255) / 256, 256>>>(w_proj, wb + WB_PROJ, 180, 180, 192, 192);
    convw_kernel<<<(384 * 192 + 255) / 256, 256>>>(ffn_w1, wb + WB_FFN1, 360, 180, 384, 192);
    convw_kernel<<<(192 * 384 + 255) / 256, 256>>>(ffn_w2, wb + WB_FFN2, 180, 360, 192, 384);

    // 1) ln1: x -> n1b (bf16, padded)
    ln_kernel<<<MROWS / 4, 128>>>(x, n1_g, n1_b, n1b);

    // 2) qkv = n1 @ w_qkv^T  (bf16 out, N=540, stride 540, 9 n-tiles)
    mma_gemm_p<0,1><<<MROWS / 128, 256, PSMEM1>>>(n1b, wb + WB_QKV, nullptr, nullptr, qkvb, 540, KP1, 540, 9);

    // 3) window attention -> n2b (bf16, padded)
    attn_kernel<<<NWIN, 384, ATTN_SMEM>>>(qkvb, b_rel, n2b);

    // 4) proj: attnf = attn @ w_proj^T + b_proj  (fp32 out)
    mma_gemm_p<1,0><<<MROWS / 128, 256, PSMEM1>>>(n2b, wb + WB_PROJ, b_proj, attnf, nullptr, 180, KP1, 180, 3);

    // 5) conv branch: dwconv(n1b)+GELU -> conv (fp32), fused mean-pool
    cudaMemsetAsync(pooled, 0, BB * CC * sizeof(float));
    dwconv_tile<bf16, float, CC, KP1, CC, 1, 1, 4><<<dim3(WWID / 4, 4, BB), CC>>>(n1b, conv_dw, conv, pooled);

    // 6) channel gate -> cm
    gate_kernel<<<BB, CC>>>(pooled, cg_w1, cg_w2, cm);

    // 7) fused residual + ln2: xmid (fp32), n2 -> n2b (bf16)
    resid_ln_kernel<<<MROWS / 4, 128>>>(x, attnf, conv, cm, n2_g, n2_b, xmid, n2b);

    // 8) ffn1: h = gelu(n2 @ ffn_w1^T) -> qkvb buffer (bf16, stride 384, N=360)
    mma_gemm_p<2,1><<<MROWS / 128, 256, PSMEM1>>>(n2b, wb + WB_FFN1, nullptr, nullptr, qkvb, 360, KP1, 384, 6);

    // 9) ffn dwconv: hsb = dwconv(h) (bf16 in stride 384, bf16 out padded 384)
    dwconv_tile<bf16, bf16, CFFN, KP2, KP2, 0, 0, 4><<<dim3(WWID / 4, 4, BB), CFFN>>>(qkvb, ffn_dw, hsb, nullptr);

    // 10) ffn2 + residual: out = xmid + hsb @ ffn_w2^T  (pipelined, KP=384)
    mma_gemm_res<<<dim3(MROWS / 128, 3), 256, PIPE_SMEM>>>(hsb, wb + WB_FFN2, xmid, out, 180, KP2);
}